// round 4
// baseline (speedup 1.0000x reference)
#include <cuda_runtime.h>

// BigramLM fused kernel for GB300 (sm_103a)
// Strategy:
//  - q/k/v depend only on (token, position): 65*8 = 520 rows -> precompute tables.
//  - q.k dots depend only on (t,tok_t,s,tok_s): precompute 4.33MB L2-resident table
//    (scale 1/sqrt(32) baked in), 4 heads packed per float4.
//  - Main kernel: 1 thread per (b,t) row. Attention = table lookups + weighted V sum
//    from padded smem V-table. FF + logits use packed fp32 FFMA2 (fma.rn.f32x2) with
//    smem weights loaded as ulonglong2 (LDS.128 -> b64 reg pairs, no repack).
//  - Logits staged in smem (aliasing the dead V-table) and flushed as coalesced float4.

#define VOCAB 65
#define NE    32
#define TT    8
#define NROWTAB 520        // 65 * 8, row index r = s*65 + tok
#define ROWS  256          // (b,t) rows per CTA
#define VT_STRIDE 36       // floats; 144B rows: 16B-aligned, bank-friendly

// shared memory layout (float offsets)
#define SM_VT   0                    // 520*36 = 18720 floats (aliased later: stage 256*65=16640)
#define SM_WF   18720                // 32*36  = 1152
#define SM_WL   (18720 + 1152)       // 19872 : 32*68 = 2176
#define SM_BF   (19872 + 2176)       // 22048 : 32
#define SM_BL   (22048 + 32)         // 22080 : 68 (65 used)
#define SM_IDXI (22080 + 68)         // 22148 : 256 ints
#define SM_FLOATS (22148 + 256)      // 22404
#define SMEM_BYTES (SM_FLOATS * 4)   // 89616 B -> 2 CTAs/SM

// ---------------- scratch (static __device__, allowed) ----------------
__device__ float  g_q[NROWTAB * NE];
__device__ float  g_k[NROWTAB * NE];
__device__ float  g_v[NROWTAB * NE];
__device__ float4 g_qk[TT * VOCAB * TT * VOCAB];  // [t][tok_t][s][tok_s] -> 4 heads

// ---------------- packed fp32 helpers ----------------
__device__ __forceinline__ unsigned long long pk2(float a, float b) {
    unsigned long long r;
    asm("mov.b64 %0, {%1, %2};" : "=l"(r) : "f"(a), "f"(b));
    return r;
}
__device__ __forceinline__ unsigned long long ffma2(unsigned long long a,
                                                    unsigned long long b,
                                                    unsigned long long c) {
    unsigned long long d;
    asm("fma.rn.f32x2 %0, %1, %2, %3;" : "=l"(d) : "l"(a), "l"(b), "l"(c));
    return d;
}
__device__ __forceinline__ float2 upk2(unsigned long long a) {
    float2 f;
    asm("mov.b64 {%0, %1}, %2;" : "=f"(f.x), "=f"(f.y) : "l"(a));
    return f;
}

// ---------------- kernel A: build q/k/v tables (520 rows) ----------------
__global__ void build_qkv(const float* __restrict__ tok_emb,
                          const float* __restrict__ pos_emb,
                          const float* __restrict__ Wq,
                          const float* __restrict__ Wk,
                          const float* __restrict__ Wv) {
    int r   = blockIdx.x;          // 0..519
    int s   = r / VOCAB;           // position
    int tok = r - s * VOCAB;       // token
    int lane = threadIdx.x;        // 32 lanes = 32 output cols (h*8+d)

    float x = tok_emb[tok * NE + lane] + pos_emb[s * NE + lane];
    int h = lane >> 3, d = lane & 7;

    float qa = 0.f, ka = 0.f, va = 0.f;
    #pragma unroll
    for (int c = 0; c < NE; c++) {
        float xc = __shfl_sync(0xffffffffu, x, c);
        int wi = (h * NE + c) * 8 + d;     // W[h][c][d]
        qa = fmaf(xc, Wq[wi], qa);
        ka = fmaf(xc, Wk[wi], ka);
        va = fmaf(xc, Wv[wi], va);
    }
    g_q[r * NE + lane] = qa;
    g_k[r * NE + lane] = ka;
    g_v[r * NE + lane] = va;
}

// ---------------- kernel B: build q.k dot table ----------------
__global__ void build_qk(void) {
    int id = blockIdx.x * 256 + threadIdx.x;
    const int TOTAL = TT * VOCAB * TT * VOCAB;   // 270400
    if (id >= TOTAL) return;
    // id = ((t*65 + tokt)*8 + s)*65 + toks
    int toks = id % VOCAB;
    int r2   = id / VOCAB;
    int s    = r2 & 7;
    int r3   = r2 >> 3;
    int tokt = r3 % VOCAB;
    int t    = r3 / VOCAB;

    int rq = t * VOCAB + tokt;
    int rk = s * VOCAB + toks;

    float dot[4];
    #pragma unroll
    for (int h = 0; h < 4; h++) {
        float acc = 0.f;
        #pragma unroll
        for (int d = 0; d < 8; d++)
            acc = fmaf(g_q[rq * NE + h * 8 + d], g_k[rk * NE + h * 8 + d], acc);
        dot[h] = acc * 0.17677669529663687f;    // 1/sqrt(N_EMBED=32), per reference
    }
    g_qk[id] = make_float4(dot[0], dot[1], dot[2], dot[3]);
}

// ---------------- main fused kernel ----------------
__global__ void __launch_bounds__(256, 2)
bigram_main(const int*   __restrict__ idx,
            const float* __restrict__ Wf,
            const float* __restrict__ bf,
            const float* __restrict__ Wl,
            const float* __restrict__ bl,
            float*       __restrict__ out) {
    extern __shared__ float sm[];
    float* VT  = sm + SM_VT;
    float* WFs = sm + SM_WF;
    float* WLs = sm + SM_WL;
    float* BFs = sm + SM_BF;
    float* BLs = sm + SM_BL;
    int*   IDX = reinterpret_cast<int*>(sm + SM_IDXI);

    const int tid = threadIdx.x;
    const int cta = blockIdx.x;

    // ---- cooperative smem init ----
    for (int i = tid; i < NROWTAB * NE; i += 256)
        VT[(i >> 5) * VT_STRIDE + (i & 31)] = g_v[i];
    for (int i = tid; i < 32 * 32; i += 256)
        WFs[(i >> 5) * 36 + (i & 31)] = Wf[i];
    for (int i = tid; i < 32 * 65; i += 256)
        WLs[(i / 65) * 68 + (i % 65)] = Wl[i];
    if (tid < 32) BFs[tid] = bf[tid];
    if (tid < 68) BLs[tid] = (tid < 65) ? bl[tid] : 0.f;
    IDX[tid] = idx[cta * ROWS + tid];
    __syncthreads();

    const int t = tid & 7;        // position of this row
    const int e = tid >> 3;       // local batch element

    int toks[8];
    #pragma unroll
    for (int s = 0; s < 8; s++) toks[s] = IDX[e * 8 + s];
    const int mytok = toks[t];

    // ---- attention: QK table lookups (L2) ----
    float4 w4[8];
    #pragma unroll
    for (int s = 0; s < 8; s++) {
        if (s <= t) {
            int lin = ((t * VOCAB + mytok) * 8 + s) * VOCAB + toks[s];
            w4[s] = g_qk[lin];
        }
    }

    float x2[32];
    #pragma unroll
    for (int h = 0; h < 4; h++) {
        float p[8];
        float ssum = 0.f;
        #pragma unroll
        for (int s = 0; s < 8; s++) {
            if (s <= t) {
                float wv = (h == 0) ? w4[s].x : (h == 1) ? w4[s].y
                         : (h == 2) ? w4[s].z : w4[s].w;
                p[s] = __expf(wv);
                ssum += p[s];
            }
        }
        float inv = __fdividef(1.f, ssum);

        float oh[8] = {0.f, 0.f, 0.f, 0.f, 0.f, 0.f, 0.f, 0.f};
        #pragma unroll
        for (int s = 0; s < 8; s++) {
            if (s <= t) {
                const float* vr = &VT[(s * VOCAB + toks[s]) * VT_STRIDE + h * 8];
                float4 v0 = *reinterpret_cast<const float4*>(vr);
                float4 v1 = *reinterpret_cast<const float4*>(vr + 4);
                float ws = p[s];
                oh[0] = fmaf(ws, v0.x, oh[0]); oh[1] = fmaf(ws, v0.y, oh[1]);
                oh[2] = fmaf(ws, v0.z, oh[2]); oh[3] = fmaf(ws, v0.w, oh[3]);
                oh[4] = fmaf(ws, v1.x, oh[4]); oh[5] = fmaf(ws, v1.y, oh[5]);
                oh[6] = fmaf(ws, v1.z, oh[6]); oh[7] = fmaf(ws, v1.w, oh[7]);
            }
        }
        #pragma unroll
        for (int d = 0; d < 8; d++) x2[h * 8 + d] = oh[d] * inv;
    }

    // ---- FF: ff = relu(x2 @ Wf + bf), packed fp32 ----
    unsigned long long ffa[16];
    #pragma unroll
    for (int pr = 0; pr < 16; pr++)
        ffa[pr] = *reinterpret_cast<const unsigned long long*>(&BFs[2 * pr]);
    #pragma unroll
    for (int c = 0; c < 32; c++) {
        unsigned long long xp = pk2(x2[c], x2[c]);
        const ulonglong2* wr = reinterpret_cast<const ulonglong2*>(&WFs[c * 36]);
        #pragma unroll
        for (int q = 0; q < 8; q++) {
            ulonglong2 wv = wr[q];
            ffa[2 * q]     = ffma2(xp, wv.x, ffa[2 * q]);
            ffa[2 * q + 1] = ffma2(xp, wv.y, ffa[2 * q + 1]);
        }
    }
    float ff[32];
    #pragma unroll
    for (int pr = 0; pr < 16; pr++) {
        float2 f = upk2(ffa[pr]);
        ff[2 * pr]     = fmaxf(f.x, 0.f);
        ff[2 * pr + 1] = fmaxf(f.y, 0.f);
    }

    // ---- logits -> smem stage (VT region is dead after this barrier) ----
    __syncthreads();
    float* STAGE = VT;   // 256*65 floats, tight layout matching global

    #pragma unroll
    for (int half = 0; half < 2; half++) {
        const int jb = half * 32;
        unsigned long long acc[16];
        #pragma unroll
        for (int pr = 0; pr < 16; pr++)
            acc[pr] = *reinterpret_cast<const unsigned long long*>(&BLs[jb + 2 * pr]);
        float accL = BLs[64];

        #pragma unroll
        for (int c = 0; c < 32; c++) {
            unsigned long long fp = pk2(ff[c], ff[c]);
            const ulonglong2* wr = reinterpret_cast<const ulonglong2*>(&WLs[c * 68 + jb]);
            #pragma unroll
            for (int q = 0; q < 8; q++) {
                ulonglong2 wv = wr[q];
                acc[2 * q]     = ffma2(fp, wv.x, acc[2 * q]);
                acc[2 * q + 1] = ffma2(fp, wv.y, acc[2 * q + 1]);
            }
            if (half == 1) accL = fmaf(ff[c], WLs[c * 68 + 64], accL);
        }
        #pragma unroll
        for (int pr = 0; pr < 16; pr++) {
            float2 f = upk2(acc[pr]);
            STAGE[tid * 65 + jb + 2 * pr]     = f.x;
            STAGE[tid * 65 + jb + 2 * pr + 1] = f.y;
        }
        if (half == 1) STAGE[tid * 65 + 64] = accL;
    }

    // ---- coalesced flush: 256 rows * 65 floats = 4160 float4 ----
    __syncthreads();
    float4*       og  = reinterpret_cast<float4*>(out) + (size_t)cta * 4160;
    const float4* st4 = reinterpret_cast<const float4*>(STAGE);
    for (int i = tid; i < 4160; i += 256) og[i] = st4[i];
}

// ---------------- launch ----------------
extern "C" void kernel_launch(void* const* d_in, const int* in_sizes, int n_in,
                              void* d_out, int out_size) {
    const int*   idx     = (const int*)  d_in[0];
    const float* tok_emb = (const float*)d_in[1];
    const float* pos_emb = (const float*)d_in[2];
    const float* Wq      = (const float*)d_in[3];
    const float* Wk      = (const float*)d_in[4];
    const float* Wv      = (const float*)d_in[5];
    const float* Wf      = (const float*)d_in[6];
    const float* bf      = (const float*)d_in[7];
    const float* Wl      = (const float*)d_in[8];
    const float* bl      = (const float*)d_in[9];
    float* out = (float*)d_out;

    build_qkv<<<NROWTAB, 32>>>(tok_emb, pos_emb, Wq, Wk, Wv);
    build_qk<<<(TT * VOCAB * TT * VOCAB + 255) / 256, 256>>>();

    cudaFuncSetAttribute(bigram_main,
                         cudaFuncAttributeMaxDynamicSharedMemorySize, SMEM_BYTES);
    int n_rows = in_sizes[0];                 // B * T = 1,048,576
    int grid   = n_rows / ROWS;               // 4096
    bigram_main<<<grid, ROWS, SMEM_BYTES>>>(idx, Wf, bf, Wl, bl, out);
}

// round 9
// speedup vs baseline: 1.4754x; 1.4754x over previous
#include <cuda_runtime.h>
#include <cuda_bf16.h>
#include <cstdint>

// BigramLM fused kernel for GB300 (sm_103a) — warp-level bf16 HMMA edition.
// tcgen05 is rejected by this harness's compute_103 PTX stage, so tensor work
// goes through mma.sync.m16n8k16 (bf16 in, fp32 accum), 3-term hi/lo split.
//  - q/k/v + QK dot tables precomputed (L2-resident).
//  - Persistent kernel, warp-decoupled: each warp owns 32-row tiles, no
//    __syncthreads in the main loop (only __syncwarp).
//  - FF GEMM: [32x32]@[32x32]; logits GEMM: [32x32]@[32x72(pad)].
//  - GEMM1 D-fragments -> relu -> GEMM2 A-fragments entirely in registers.
//  - Per-warp smem stage (stride 68) -> coalesced float4 flush.

#define VOCAB 65
#define NE    32
#define TT    8
#define NROWTAB 520
#define VT_STRIDE 36

// ---- smem byte offsets ----
#define OFF_BF     0          // 32 f
#define OFF_BL     128        // 72 f
#define OFF_B1HI   416        // 32 rows * 20 words * 4B = 2560
#define OFF_B1LO   2976
#define OFF_B2HI   5536       // 72 rows * 20 words * 4B = 5760
#define OFF_B2LO   11296
#define OFF_VT     17056      // 520*36 floats = 74880
#define OFF_XW     91936      // 8 warps * 32 rows * 33 words * 4B = 33792
#define OFF_STAGE  125728     // 8 warps * 32*68 floats = 69632
#define SMEM_TOTAL 195360

// ---------------- scratch ----------------
__device__ float  g_q[NROWTAB * NE];
__device__ float  g_k[NROWTAB * NE];
__device__ float  g_v[NROWTAB * NE];
__device__ float4 g_qk[TT * VOCAB * TT * VOCAB];

// ---------------- helpers ----------------
__device__ __forceinline__ uint32_t pkbf(float lo, float hi) {
    uint32_t r;
    asm("cvt.rn.bf16x2.f32 %0, %1, %2;" : "=r"(r) : "f"(hi), "f"(lo));
    return r;
}
__device__ __forceinline__ void split_bf(const float* x, uint32_t* hi, uint32_t* lo) {
    #pragma unroll
    for (int p = 0; p < 16; p++) {
        float x0 = x[2 * p], x1 = x[2 * p + 1];
        uint32_t h = pkbf(x0, x1);
        float r0 = x0 - __uint_as_float(h << 16);
        float r1 = x1 - __uint_as_float(h & 0xffff0000u);
        hi[p] = h;
        lo[p] = pkbf(r0, r1);
    }
}
__device__ __forceinline__ void mma16816(float* d, const uint32_t* a,
                                         uint32_t b0, uint32_t b1) {
    asm volatile(
        "mma.sync.aligned.m16n8k16.row.col.f32.bf16.bf16.f32 "
        "{%0,%1,%2,%3}, {%4,%5,%6,%7}, {%8,%9}, {%0,%1,%2,%3};"
        : "+f"(d[0]), "+f"(d[1]), "+f"(d[2]), "+f"(d[3])
        : "r"(a[0]), "r"(a[1]), "r"(a[2]), "r"(a[3]), "r"(b0), "r"(b1));
}

// ---------------- kernel A: build q/k/v tables ----------------
__global__ void build_qkv(const float* __restrict__ tok_emb,
                          const float* __restrict__ pos_emb,
                          const float* __restrict__ Wq,
                          const float* __restrict__ Wk,
                          const float* __restrict__ Wv) {
    int r    = blockIdx.x * 8 + (threadIdx.x >> 5);
    int lane = threadIdx.x & 31;
    if (r >= NROWTAB) return;
    int s = r / VOCAB, tok = r - s * VOCAB;

    float x = tok_emb[tok * NE + lane] + pos_emb[s * NE + lane];
    int h = lane >> 3, d = lane & 7;

    float qa = 0.f, ka = 0.f, va = 0.f;
    #pragma unroll
    for (int c = 0; c < NE; c++) {
        float xc = __shfl_sync(0xffffffffu, x, c);
        int wi = (h * NE + c) * 8 + d;
        qa = fmaf(xc, Wq[wi], qa);
        ka = fmaf(xc, Wk[wi], ka);
        va = fmaf(xc, Wv[wi], va);
    }
    g_q[r * NE + lane] = qa;
    g_k[r * NE + lane] = ka;
    g_v[r * NE + lane] = va;
}

// ---------------- kernel B: QK dot table ----------------
__global__ void build_qk(void) {
    int id = blockIdx.x * 256 + threadIdx.x;
    const int TOTAL = TT * VOCAB * TT * VOCAB;
    if (id >= TOTAL) return;
    int toks = id % VOCAB;
    int r2   = id / VOCAB;
    int s    = r2 & 7;
    int r3   = r2 >> 3;
    int tokt = r3 % VOCAB;
    int t    = r3 / VOCAB;

    int rq = t * VOCAB + tokt;
    int rk = s * VOCAB + toks;

    float dot[4];
    #pragma unroll
    for (int h = 0; h < 4; h++) {
        float acc = 0.f;
        #pragma unroll
        for (int d = 0; d < 8; d++)
            acc = fmaf(g_q[rq * NE + h * 8 + d], g_k[rk * NE + h * 8 + d], acc);
        dot[h] = acc * 0.17677669529663687f;   // 1/sqrt(N_EMBED)
    }
    g_qk[id] = make_float4(dot[0], dot[1], dot[2], dot[3]);
}

// ---------------- main persistent kernel ----------------
__global__ void __launch_bounds__(256, 1)
bigram_main(const int*   __restrict__ idx,
            const float* __restrict__ Wf,
            const float* __restrict__ bf,
            const float* __restrict__ Wl,
            const float* __restrict__ bl,
            float*       __restrict__ out,
            int n_wtiles) {
    extern __shared__ char sm[];
    float* BFs = (float*)(sm + OFF_BF);
    float* BLs = (float*)(sm + OFF_BL);
    float* VT  = (float*)(sm + OFF_VT);
    const int tid = threadIdx.x;

    // ---- one-time init ----
    for (int i = tid; i < NROWTAB * NE; i += 256)
        VT[(i >> 5) * VT_STRIDE + (i & 31)] = g_v[i];
    if (tid < 32) BFs[tid] = bf[tid];
    if (tid < 72) BLs[tid] = (tid < 65) ? bl[tid] : 0.f;

    // B1 = WfT (row n, word j = k cols 2j,2j+1), row stride 20 words
    for (int i = tid; i < 32 * 32; i += 256) {
        int k = i >> 5, n = i & 31;
        float w = Wf[i];
        __nv_bfloat16 hb = __float2bfloat16(w);
        __nv_bfloat16 lb = __float2bfloat16(w - __bfloat162float(hb));
        int e = (n * 20 + (k >> 1)) * 2 + (k & 1);
        ((__nv_bfloat16*)(sm + OFF_B1HI))[e] = hb;
        ((__nv_bfloat16*)(sm + OFF_B1LO))[e] = lb;
    }
    // B2 = WlT, rows 65..71 zero
    for (int i = tid; i < 72 * 20; i += 256) {
        ((uint32_t*)(sm + OFF_B2HI))[i] = 0u;
        ((uint32_t*)(sm + OFF_B2LO))[i] = 0u;
    }
    __syncthreads();
    for (int i = tid; i < 32 * 65; i += 256) {
        int k = i / 65, n = i % 65;
        float w = Wl[i];
        __nv_bfloat16 hb = __float2bfloat16(w);
        __nv_bfloat16 lb = __float2bfloat16(w - __bfloat162float(hb));
        int e = (n * 20 + (k >> 1)) * 2 + (k & 1);
        ((__nv_bfloat16*)(sm + OFF_B2HI))[e] = hb;
        ((__nv_bfloat16*)(sm + OFF_B2LO))[e] = lb;
    }
    __syncthreads();

    const int wid = tid >> 5, l = tid & 31;
    const int lq = l >> 2, lr = l & 3;         // fragment row group / col group
    const int t = l & 7;                       // sequence position of this lane's row
    uint32_t*       XW = (uint32_t*)(sm + OFF_XW) + wid * (32 * 33);
    float*          ST = (float*)(sm + OFF_STAGE) + wid * (32 * 68);
    const uint32_t* B1H = (const uint32_t*)(sm + OFF_B1HI);
    const uint32_t* B1L = (const uint32_t*)(sm + OFF_B1LO);
    const uint32_t* B2H = (const uint32_t*)(sm + OFF_B2HI);
    const uint32_t* B2L = (const uint32_t*)(sm + OFF_B2LO);

    const int wstride = gridDim.x * 8;
    for (int wt = blockIdx.x * 8 + wid; wt < n_wtiles; wt += wstride) {
        // ---- tokens via warp shuffle ----
        int tk = idx[wt * 32 + l];
        int toks[8];
        #pragma unroll
        for (int s = 0; s < 8; s++)
            toks[s] = __shfl_sync(0xffffffffu, tk, (l & 24) | s);

        // ---- attention (fp32, table-driven) ----
        float4 w4[8];
        #pragma unroll
        for (int s = 0; s < 8; s++)
            if (s <= t)
                w4[s] = g_qk[((t * VOCAB + tk) * 8 + s) * VOCAB + toks[s]];

        float x2[32];
        #pragma unroll
        for (int h = 0; h < 4; h++) {
            float p[8], ssum = 0.f;
            #pragma unroll
            for (int s = 0; s < 8; s++) {
                if (s <= t) {
                    float wv = (h == 0) ? w4[s].x : (h == 1) ? w4[s].y
                             : (h == 2) ? w4[s].z : w4[s].w;
                    p[s] = __expf(wv);
                    ssum += p[s];
                }
            }
            float inv = __fdividef(1.f, ssum);
            float oh[8] = {0.f, 0.f, 0.f, 0.f, 0.f, 0.f, 0.f, 0.f};
            #pragma unroll
            for (int s = 0; s < 8; s++) {
                if (s <= t) {
                    const float* vr = &VT[(s * VOCAB + toks[s]) * VT_STRIDE + h * 8];
                    float4 v0 = *reinterpret_cast<const float4*>(vr);
                    float4 v1 = *reinterpret_cast<const float4*>(vr + 4);
                    float ws = p[s];
                    oh[0] = fmaf(ws, v0.x, oh[0]); oh[1] = fmaf(ws, v0.y, oh[1]);
                    oh[2] = fmaf(ws, v0.z, oh[2]); oh[3] = fmaf(ws, v0.w, oh[3]);
                    oh[4] = fmaf(ws, v1.x, oh[4]); oh[5] = fmaf(ws, v1.y, oh[5]);
                    oh[6] = fmaf(ws, v1.z, oh[6]); oh[7] = fmaf(ws, v1.w, oh[7]);
                }
            }
            #pragma unroll
            for (int d = 0; d < 8; d++) x2[h * 8 + d] = oh[d] * inv;
        }

        // ---- stage x2 as split bf16 (row l, words 0..15 hi, 16..31 lo) ----
        {
            uint32_t hi[16], lo[16];
            split_bf(x2, hi, lo);
            uint32_t* xr = XW + l * 33;
            #pragma unroll
            for (int p = 0; p < 16; p++) { xr[p] = hi[p]; xr[16 + p] = lo[p]; }
        }
        __syncwarp();

        // ---- A fragments for GEMM1 ----
        uint32_t ah[2][2][4], al[2][2][4];
        #pragma unroll
        for (int m = 0; m < 2; m++) {
            int r0 = (m * 16 + lq) * 33, r1 = r0 + 8 * 33;
            #pragma unroll
            for (int k = 0; k < 2; k++) {
                int w0 = 8 * k + lr;
                ah[m][k][0] = XW[r0 + w0];     ah[m][k][1] = XW[r1 + w0];
                ah[m][k][2] = XW[r0 + w0 + 4]; ah[m][k][3] = XW[r1 + w0 + 4];
                al[m][k][0] = XW[r0 + 16 + w0];     al[m][k][1] = XW[r1 + 16 + w0];
                al[m][k][2] = XW[r0 + 16 + w0 + 4]; al[m][k][3] = XW[r1 + 16 + w0 + 4];
            }
        }

        // ---- GEMM1: D1 = X @ WfT (3-term split) ----
        float D1[2][4][4];
        #pragma unroll
        for (int m = 0; m < 2; m++)
            #pragma unroll
            for (int n = 0; n < 4; n++)
                #pragma unroll
                for (int q = 0; q < 4; q++) D1[m][n][q] = 0.f;

        #pragma unroll
        for (int nt = 0; nt < 4; nt++) {
            int bro = (nt * 8 + lq) * 20;
            #pragma unroll
            for (int k = 0; k < 2; k++) {
                uint32_t bh0 = B1H[bro + 8 * k + lr], bh1 = B1H[bro + 8 * k + 4 + lr];
                uint32_t bl0 = B1L[bro + 8 * k + lr], bl1 = B1L[bro + 8 * k + 4 + lr];
                #pragma unroll
                for (int m = 0; m < 2; m++) {
                    mma16816(D1[m][nt], ah[m][k], bh0, bh1);
                    mma16816(D1[m][nt], ah[m][k], bl0, bl1);
                    mma16816(D1[m][nt], al[m][k], bh0, bh1);
                }
            }
        }

        // ---- relu(+bias) -> GEMM2 A fragments (registers only) ----
        uint32_t fh[2][2][4], fl[2][2][4];
        #pragma unroll
        for (int m = 0; m < 2; m++) {
            #pragma unroll
            for (int nt = 0; nt < 4; nt++) {
                int col = nt * 8 + lr * 2;
                float c0 = fmaxf(D1[m][nt][0] + BFs[col],     0.f);
                float c1 = fmaxf(D1[m][nt][1] + BFs[col + 1], 0.f);
                float c2 = fmaxf(D1[m][nt][2] + BFs[col],     0.f);
                float c3 = fmaxf(D1[m][nt][3] + BFs[col + 1], 0.f);
                uint32_t h01 = pkbf(c0, c1);
                uint32_t h23 = pkbf(c2, c3);
                float r0 = c0 - __uint_as_float(h01 << 16);
                float r1 = c1 - __uint_as_float(h01 & 0xffff0000u);
                float r2 = c2 - __uint_as_float(h23 << 16);
                float r3 = c3 - __uint_as_float(h23 & 0xffff0000u);
                int K = nt >> 1, pc = nt & 1;
                fh[m][K][2 * pc]     = h01;
                fh[m][K][2 * pc + 1] = h23;
                fl[m][K][2 * pc]     = pkbf(r0, r1);
                fl[m][K][2 * pc + 1] = pkbf(r2, r3);
            }
        }

        // ---- GEMM2: logits = FF @ WlT (N padded to 72) -> stage ----
        #pragma unroll
        for (int nt = 0; nt < 9; nt++) {
            int bro = (nt * 8 + lq) * 20;
            uint32_t bh[2][2], blw[2][2];
            #pragma unroll
            for (int k = 0; k < 2; k++) {
                bh[k][0]  = B2H[bro + 8 * k + lr];  bh[k][1]  = B2H[bro + 8 * k + 4 + lr];
                blw[k][0] = B2L[bro + 8 * k + lr];  blw[k][1] = B2L[bro + 8 * k + 4 + lr];
            }
            #pragma unroll
            for (int m = 0; m < 2; m++) {
                float D2[4] = {0.f, 0.f, 0.f, 0.f};
                #pragma unroll
                for (int k = 0; k < 2; k++) {
                    mma16816(D2, fh[m][k], bh[k][0],  bh[k][1]);
                    mma16816(D2, fh[m][k], blw[k][0], blw[k][1]);
                    mma16816(D2, fl[m][k], bh[k][0],  bh[k][1]);
                }
                int col = nt * 8 + lr * 2;
                int r0 = (m * 16 + lq) * 68, r1 = r0 + 8 * 68;
                if (nt < 8) {
                    float2 v0 = make_float2(D2[0] + BLs[col], D2[1] + BLs[col + 1]);
                    float2 v1 = make_float2(D2[2] + BLs[col], D2[3] + BLs[col + 1]);
                    *(float2*)&ST[r0 + col] = v0;
                    *(float2*)&ST[r1 + col] = v1;
                } else if (lr == 0) {
                    ST[r0 + 64] = D2[0] + BLs[64];
                    ST[r1 + 64] = D2[2] + BLs[64];
                }
            }
        }
        __syncwarp();

        // ---- coalesced flush: this warp's 32 rows = 2080 floats = 520 float4 ----
        float4* og = reinterpret_cast<float4*>(out) + (size_t)wt * 520;
        for (int i = l; i < 520; i += 32) {
            int f = i * 4;
            int r = f / 65;
            int c = f - r * 65;
            float v[4];
            #pragma unroll
            for (int j = 0; j < 4; j++) {
                v[j] = ST[r * 68 + c];
                if (++c == 65) { c = 0; r++; }
            }
            og[i] = make_float4(v[0], v[1], v[2], v[3]);
        }
        __syncwarp();
    }
}

// ---------------- launch ----------------
extern "C" void kernel_launch(void* const* d_in, const int* in_sizes, int n_in,
                              void* d_out, int out_size) {
    const int*   idx     = (const int*)  d_in[0];
    const float* tok_emb = (const float*)d_in[1];
    const float* pos_emb = (const float*)d_in[2];
    const float* Wq      = (const float*)d_in[3];
    const float* Wk      = (const float*)d_in[4];
    const float* Wv      = (const float*)d_in[5];
    const float* Wf      = (const float*)d_in[6];
    const float* bf      = (const float*)d_in[7];
    const float* Wl      = (const float*)d_in[8];
    const float* bl      = (const float*)d_in[9];
    float* out = (float*)d_out;

    build_qkv<<<65, 256>>>(tok_emb, pos_emb, Wq, Wk, Wv);
    build_qk<<<(TT * VOCAB * TT * VOCAB + 255) / 256, 256>>>();

    int dev = 0, smc = 148;
    cudaGetDevice(&dev);
    cudaDeviceGetAttribute(&smc, cudaDevAttrMultiProcessorCount, dev);

    cudaFuncSetAttribute(bigram_main,
                         cudaFuncAttributeMaxDynamicSharedMemorySize, SMEM_TOTAL);
    int n_wtiles = in_sizes[0] / 32;     // 1,048,576 / 32 = 32768
    bigram_main<<<smc, 256, SMEM_TOTAL>>>(idx, Wf, bf, Wl, bl, out, n_wtiles);
}

// round 10
// speedup vs baseline: 1.9777x; 1.3405x over previous
#include <cuda_runtime.h>
#include <cuda_bf16.h>
#include <cstdint>

// BigramLM fused kernel for GB300 (sm_103a) — HMMA + high-occupancy edition.
//  - QK table now stores exp(q.k*scale): softmax in-loop is pure adds.
//  - 512 threads (16 warps -> 4/SMSP), per-warp smem shrunk to 4.35KB by
//    aliasing the A-fragment staging (XW) with a 16-row logits stage and
//    flushing GEMM2 per m-half.
//  - FF/logits via mma.sync m16n8k16 bf16, 3-term hi/lo split (fp32 accuracy).

#define VOCAB 65
#define NE    32
#define TT    8
#define NROWTAB 520
#define VT_STRIDE 36
#define NWARP 16

// ---- smem byte offsets ----
#define OFF_BF     0          // 32 f
#define OFF_BL     128        // 72 f
#define OFF_B1HI   416        // 32 rows * 20 words * 4B = 2560
#define OFF_B1LO   2976
#define OFF_B2HI   5536       // 72 rows * 20 words * 4B = 5760
#define OFF_B2LO   11296
#define OFF_VT     17056      // 520*36 floats = 74880
#define OFF_WARP   91936      // 16 warps * 4352B (XW 4224B aliased with 16x68-f stage)
#define WARP_BYTES 4352
#define SMEM_TOTAL (91936 + NWARP * WARP_BYTES)   // 161568

// ---------------- scratch ----------------
__device__ float  g_q[NROWTAB * NE];
__device__ float  g_k[NROWTAB * NE];
__device__ float  g_v[NROWTAB * NE];
__device__ float4 g_qk[TT * VOCAB * TT * VOCAB];   // exp(dot*scale), 4 heads

// ---------------- helpers ----------------
__device__ __forceinline__ uint32_t pkbf(float lo, float hi) {
    uint32_t r;
    asm("cvt.rn.bf16x2.f32 %0, %1, %2;" : "=r"(r) : "f"(hi), "f"(lo));
    return r;
}
__device__ __forceinline__ void split_bf(const float* x, uint32_t* hi, uint32_t* lo) {
    #pragma unroll
    for (int p = 0; p < 16; p++) {
        float x0 = x[2 * p], x1 = x[2 * p + 1];
        uint32_t h = pkbf(x0, x1);
        float r0 = x0 - __uint_as_float(h << 16);
        float r1 = x1 - __uint_as_float(h & 0xffff0000u);
        hi[p] = h;
        lo[p] = pkbf(r0, r1);
    }
}
__device__ __forceinline__ void mma16816(float* d, const uint32_t* a,
                                         uint32_t b0, uint32_t b1) {
    asm volatile(
        "mma.sync.aligned.m16n8k16.row.col.f32.bf16.bf16.f32 "
        "{%0,%1,%2,%3}, {%4,%5,%6,%7}, {%8,%9}, {%0,%1,%2,%3};"
        : "+f"(d[0]), "+f"(d[1]), "+f"(d[2]), "+f"(d[3])
        : "r"(a[0]), "r"(a[1]), "r"(a[2]), "r"(a[3]), "r"(b0), "r"(b1));
}

// ---------------- kernel A: build q/k/v tables ----------------
__global__ void build_qkv(const float* __restrict__ tok_emb,
                          const float* __restrict__ pos_emb,
                          const float* __restrict__ Wq,
                          const float* __restrict__ Wk,
                          const float* __restrict__ Wv) {
    int r    = blockIdx.x * 8 + (threadIdx.x >> 5);
    int lane = threadIdx.x & 31;
    if (r >= NROWTAB) return;
    int s = r / VOCAB, tok = r - s * VOCAB;

    float x = tok_emb[tok * NE + lane] + pos_emb[s * NE + lane];
    int h = lane >> 3, d = lane & 7;

    float qa = 0.f, ka = 0.f, va = 0.f;
    #pragma unroll
    for (int c = 0; c < NE; c++) {
        float xc = __shfl_sync(0xffffffffu, x, c);
        int wi = (h * NE + c) * 8 + d;
        qa = fmaf(xc, Wq[wi], qa);
        ka = fmaf(xc, Wk[wi], ka);
        va = fmaf(xc, Wv[wi], va);
    }
    g_q[r * NE + lane] = qa;
    g_k[r * NE + lane] = ka;
    g_v[r * NE + lane] = va;
}

// ---------------- kernel B: QK exp table ----------------
__global__ void build_qk(void) {
    int id = blockIdx.x * 256 + threadIdx.x;
    const int TOTAL = TT * VOCAB * TT * VOCAB;
    if (id >= TOTAL) return;
    int toks = id % VOCAB;
    int r2   = id / VOCAB;
    int s    = r2 & 7;
    int r3   = r2 >> 3;
    int tokt = r3 % VOCAB;
    int t    = r3 / VOCAB;

    int rq = t * VOCAB + tokt;
    int rk = s * VOCAB + toks;

    float dot[4];
    #pragma unroll
    for (int h = 0; h < 4; h++) {
        float acc = 0.f;
        #pragma unroll
        for (int d = 0; d < 8; d++)
            acc = fmaf(g_q[rq * NE + h * 8 + d], g_k[rk * NE + h * 8 + d], acc);
        dot[h] = expf(acc * 0.17677669529663687f);   // exp baked in
    }
    g_qk[id] = make_float4(dot[0], dot[1], dot[2], dot[3]);
}

// ---------------- main persistent kernel ----------------
__global__ void __launch_bounds__(512, 1)
bigram_main(const int*   __restrict__ idx,
            const float* __restrict__ Wf,
            const float* __restrict__ bf,
            const float* __restrict__ Wl,
            const float* __restrict__ bl,
            float*       __restrict__ out,
            int n_wtiles) {
    extern __shared__ char sm[];
    float* BFs = (float*)(sm + OFF_BF);
    float* BLs = (float*)(sm + OFF_BL);
    float* VT  = (float*)(sm + OFF_VT);
    const int tid = threadIdx.x;

    // ---- one-time init ----
    for (int i = tid; i < NROWTAB * NE; i += 512)
        VT[(i >> 5) * VT_STRIDE + (i & 31)] = g_v[i];
    if (tid < 32) BFs[tid] = bf[tid];
    if (tid < 72) BLs[tid] = (tid < 65) ? bl[tid] : 0.f;

    // B1 = WfT (row n, word j = k cols 2j,2j+1), row stride 20 words
    for (int i = tid; i < 32 * 32; i += 512) {
        int k = i >> 5, n = i & 31;
        float w = Wf[i];
        __nv_bfloat16 hb = __float2bfloat16(w);
        __nv_bfloat16 lb = __float2bfloat16(w - __bfloat162float(hb));
        int e = (n * 20 + (k >> 1)) * 2 + (k & 1);
        ((__nv_bfloat16*)(sm + OFF_B1HI))[e] = hb;
        ((__nv_bfloat16*)(sm + OFF_B1LO))[e] = lb;
    }
    // B2 = WlT, rows 65..71 zero
    for (int i = tid; i < 72 * 20; i += 512) {
        ((uint32_t*)(sm + OFF_B2HI))[i] = 0u;
        ((uint32_t*)(sm + OFF_B2LO))[i] = 0u;
    }
    __syncthreads();
    for (int i = tid; i < 32 * 65; i += 512) {
        int k = i / 65, n = i % 65;
        float w = Wl[i];
        __nv_bfloat16 hb = __float2bfloat16(w);
        __nv_bfloat16 lb = __float2bfloat16(w - __bfloat162float(hb));
        int e = (n * 20 + (k >> 1)) * 2 + (k & 1);
        ((__nv_bfloat16*)(sm + OFF_B2HI))[e] = hb;
        ((__nv_bfloat16*)(sm + OFF_B2LO))[e] = lb;
    }
    __syncthreads();

    const int wid = tid >> 5, l = tid & 31;
    const int lq = l >> 2, lr = l & 3;
    const int t = l & 7;
    char*           WR = sm + OFF_WARP + wid * WARP_BYTES;
    uint32_t*       XW = (uint32_t*)WR;      // 32 rows * 33 words (A-frag staging)
    float*          ST = (float*)WR;         // 16 rows * 68 floats (logits stage, aliased)
    const uint32_t* B1H = (const uint32_t*)(sm + OFF_B1HI);
    const uint32_t* B1L = (const uint32_t*)(sm + OFF_B1LO);
    const uint32_t* B2H = (const uint32_t*)(sm + OFF_B2HI);
    const uint32_t* B2L = (const uint32_t*)(sm + OFF_B2LO);

    const int wstride = gridDim.x * NWARP;
    for (int wt = blockIdx.x * NWARP + wid; wt < n_wtiles; wt += wstride) {
        // ---- tokens via warp shuffle ----
        int tk = idx[wt * 32 + l];
        int toks[8];
        #pragma unroll
        for (int s = 0; s < 8; s++)
            toks[s] = __shfl_sync(0xffffffffu, tk, (l & 24) | s);

        // ---- attention (exp pre-baked in table) ----
        float4 w4[8];
        #pragma unroll
        for (int s = 0; s < 8; s++)
            if (s <= t)
                w4[s] = g_qk[((t * VOCAB + tk) * 8 + s) * VOCAB + toks[s]];

        float x2[32];
        #pragma unroll
        for (int h = 0; h < 4; h++) {
            float p[8], ssum = 0.f;
            #pragma unroll
            for (int s = 0; s < 8; s++) {
                if (s <= t) {
                    p[s] = (h == 0) ? w4[s].x : (h == 1) ? w4[s].y
                         : (h == 2) ? w4[s].z : w4[s].w;
                    ssum += p[s];
                }
            }
            float inv = __fdividef(1.f, ssum);
            float oh[8] = {0.f, 0.f, 0.f, 0.f, 0.f, 0.f, 0.f, 0.f};
            #pragma unroll
            for (int s = 0; s < 8; s++) {
                if (s <= t) {
                    const float* vr = &VT[(s * VOCAB + toks[s]) * VT_STRIDE + h * 8];
                    float4 v0 = *reinterpret_cast<const float4*>(vr);
                    float4 v1 = *reinterpret_cast<const float4*>(vr + 4);
                    float ws = p[s];
                    oh[0] = fmaf(ws, v0.x, oh[0]); oh[1] = fmaf(ws, v0.y, oh[1]);
                    oh[2] = fmaf(ws, v0.z, oh[2]); oh[3] = fmaf(ws, v0.w, oh[3]);
                    oh[4] = fmaf(ws, v1.x, oh[4]); oh[5] = fmaf(ws, v1.y, oh[5]);
                    oh[6] = fmaf(ws, v1.z, oh[6]); oh[7] = fmaf(ws, v1.w, oh[7]);
                }
            }
            #pragma unroll
            for (int d = 0; d < 8; d++) x2[h * 8 + d] = oh[d] * inv;
        }

        // ---- stage x2 as split bf16 (row l: words 0..15 hi, 16..31 lo) ----
        {
            uint32_t hi[16], lo[16];
            split_bf(x2, hi, lo);
            uint32_t* xr = XW + l * 33;
            #pragma unroll
            for (int p = 0; p < 16; p++) { xr[p] = hi[p]; xr[16 + p] = lo[p]; }
        }
        __syncwarp();

        // ---- A fragments for GEMM1 ----
        uint32_t ah[2][2][4], al[2][2][4];
        #pragma unroll
        for (int m = 0; m < 2; m++) {
            int r0 = (m * 16 + lq) * 33, r1 = r0 + 8 * 33;
            #pragma unroll
            for (int k = 0; k < 2; k++) {
                int w0 = 8 * k + lr;
                ah[m][k][0] = XW[r0 + w0];     ah[m][k][1] = XW[r1 + w0];
                ah[m][k][2] = XW[r0 + w0 + 4]; ah[m][k][3] = XW[r1 + w0 + 4];
                al[m][k][0] = XW[r0 + 16 + w0];     al[m][k][1] = XW[r1 + 16 + w0];
                al[m][k][2] = XW[r0 + 16 + w0 + 4]; al[m][k][3] = XW[r1 + 16 + w0 + 4];
            }
        }
        __syncwarp();   // XW reads done; region may be reused as ST below

        // ---- GEMM1: D1 = X @ WfT (3-term split) ----
        float D1[2][4][4];
        #pragma unroll
        for (int m = 0; m < 2; m++)
            #pragma unroll
            for (int n = 0; n < 4; n++)
                #pragma unroll
                for (int q = 0; q < 4; q++) D1[m][n][q] = 0.f;

        #pragma unroll
        for (int nt = 0; nt < 4; nt++) {
            int bro = (nt * 8 + lq) * 20;
            #pragma unroll
            for (int k = 0; k < 2; k++) {
                uint32_t bh0 = B1H[bro + 8 * k + lr], bh1 = B1H[bro + 8 * k + 4 + lr];
                uint32_t bl0 = B1L[bro + 8 * k + lr], bl1 = B1L[bro + 8 * k + 4 + lr];
                #pragma unroll
                for (int m = 0; m < 2; m++) {
                    mma16816(D1[m][nt], ah[m][k], bh0, bh1);
                    mma16816(D1[m][nt], ah[m][k], bl0, bl1);
                    mma16816(D1[m][nt], al[m][k], bh0, bh1);
                }
            }
        }

        // ---- relu(+bias) -> GEMM2 A fragments (registers only) ----
        uint32_t fh[2][2][4], fl[2][2][4];
        #pragma unroll
        for (int m = 0; m < 2; m++) {
            #pragma unroll
            for (int nt = 0; nt < 4; nt++) {
                int col = nt * 8 + lr * 2;
                float c0 = fmaxf(D1[m][nt][0] + BFs[col],     0.f);
                float c1 = fmaxf(D1[m][nt][1] + BFs[col + 1], 0.f);
                float c2 = fmaxf(D1[m][nt][2] + BFs[col],     0.f);
                float c3 = fmaxf(D1[m][nt][3] + BFs[col + 1], 0.f);
                uint32_t h01 = pkbf(c0, c1);
                uint32_t h23 = pkbf(c2, c3);
                float r0 = c0 - __uint_as_float(h01 << 16);
                float r1 = c1 - __uint_as_float(h01 & 0xffff0000u);
                float r2 = c2 - __uint_as_float(h23 << 16);
                float r3 = c3 - __uint_as_float(h23 & 0xffff0000u);
                int K = nt >> 1, pc = nt & 1;
                fh[m][K][2 * pc]     = h01;
                fh[m][K][2 * pc + 1] = h23;
                fl[m][K][2 * pc]     = pkbf(r0, r1);
                fl[m][K][2 * pc + 1] = pkbf(r2, r3);
            }
        }

        // ---- GEMM2 per m-half: logits -> 16-row stage -> coalesced flush ----
        #pragma unroll
        for (int m = 0; m < 2; m++) {
            #pragma unroll
            for (int nt = 0; nt < 9; nt++) {
                int bro = (nt * 8 + lq) * 20;
                float D2[4] = {0.f, 0.f, 0.f, 0.f};
                #pragma unroll
                for (int k = 0; k < 2; k++) {
                    uint32_t bh0  = B2H[bro + 8 * k + lr], bh1  = B2H[bro + 8 * k + 4 + lr];
                    uint32_t blw0 = B2L[bro + 8 * k + lr], blw1 = B2L[bro + 8 * k + 4 + lr];
                    mma16816(D2, fh[m][k], bh0,  bh1);
                    mma16816(D2, fh[m][k], blw0, blw1);
                    mma16816(D2, fl[m][k], bh0,  bh1);
                }
                int col = nt * 8 + lr * 2;
                int r0 = lq * 68, r1 = r0 + 8 * 68;
                if (nt < 8) {
                    *(float2*)&ST[r0 + col] = make_float2(D2[0] + BLs[col], D2[1] + BLs[col + 1]);
                    *(float2*)&ST[r1 + col] = make_float2(D2[2] + BLs[col], D2[3] + BLs[col + 1]);
                } else if (lr == 0) {
                    ST[r0 + 64] = D2[0] + BLs[64];
                    ST[r1 + 64] = D2[2] + BLs[64];
                }
            }
            __syncwarp();

            // flush this half: 16 rows * 65 floats = 1040 f = 260 float4 (aligned)
            float4* og = reinterpret_cast<float4*>(out + ((size_t)wt * 32 + m * 16) * 65);
            for (int i = l; i < 260; i += 32) {
                int f = i * 4;
                int r = f / 65;
                int c = f - r * 65;
                float v[4];
                #pragma unroll
                for (int j = 0; j < 4; j++) {
                    v[j] = ST[r * 68 + c];
                    if (++c == 65) { c = 0; r++; }
                }
                og[i] = make_float4(v[0], v[1], v[2], v[3]);
            }
            __syncwarp();
        }
    }
}

// ---------------- launch ----------------
extern "C" void kernel_launch(void* const* d_in, const int* in_sizes, int n_in,
                              void* d_out, int out_size) {
    const int*   idx     = (const int*)  d_in[0];
    const float* tok_emb = (const float*)d_in[1];
    const float* pos_emb = (const float*)d_in[2];
    const float* Wq      = (const float*)d_in[3];
    const float* Wk      = (const float*)d_in[4];
    const float* Wv      = (const float*)d_in[5];
    const float* Wf      = (const float*)d_in[6];
    const float* bf      = (const float*)d_in[7];
    const float* Wl      = (const float*)d_in[8];
    const float* bl      = (const float*)d_in[9];
    float* out = (float*)d_out;

    build_qkv<<<65, 256>>>(tok_emb, pos_emb, Wq, Wk, Wv);
    build_qk<<<(TT * VOCAB * TT * VOCAB + 255) / 256, 256>>>();

    int dev = 0, smc = 148;
    cudaGetDevice(&dev);
    cudaDeviceGetAttribute(&smc, cudaDevAttrMultiProcessorCount, dev);

    cudaFuncSetAttribute(bigram_main,
                         cudaFuncAttributeMaxDynamicSharedMemorySize, SMEM_TOTAL);
    int n_wtiles = in_sizes[0] / 32;     // 1,048,576 / 32 = 32768
    bigram_main<<<smc, 512, SMEM_TOTAL>>>(idx, Wf, bf, Wl, bl, out, n_wtiles);
}

// round 12
// speedup vs baseline: 2.3953x; 1.2112x over previous
#include <cuda_runtime.h>
#include <cuda_bf16.h>
#include <cstdint>

// BigramLM fused kernel for GB300 (sm_103a) — HMMA, streamlined epilogue.
//  - QK table stores exp(q.k*scale); attention is adds+fma only.
//  - 512 threads persistent (4 warps/SMSP), warp-decoupled tiles of 32 rows.
//  - B fragments pre-packed as float4 per (nt,k,lane): 1 LDS.128 replaces 4 LDS.32.
//  - GEMM2 uses 3 independent 2-deep MMA chains (hi.hi/hi.lo/lo.hi) for ILP.
//  - Logits stage stride 65 -> flush is a pure contiguous float4 copy.
//  - idx prefetched one tile ahead; prologue loads coalesced via transposed q/k.

#define VOCAB 65
#define NE    32
#define TT    8
#define NROWTAB 520
#define VT_STRIDE 36
#define NWARP 16

// ---- smem byte offsets ----
#define OFF_BF     0          // 32 f
#define OFF_BL     128        // 72 f
#define OFF_B1P    416        // 256 uint4 = 4096
#define OFF_B2P    4512       // 576 uint4 = 9216
#define OFF_VT     13728      // 520*36 f = 74880
#define OFF_WARP   88608      // 16 warps * 4224 (XW 32*33 words, aliased 16x65-f stage)
#define WARP_BYTES 4224
#define SMEM_TOTAL (88608 + NWARP * WARP_BYTES)   // 156192

// ---------------- scratch ----------------
__device__ float  g_qT[NE * NROWTAB];   // transposed for coalesced build_qk
__device__ float  g_kT[NE * NROWTAB];
__device__ float  g_v [NROWTAB * NE];
__device__ float4 g_qk[TT * VOCAB * TT * VOCAB];   // exp(dot*scale), 4 heads

// ---------------- helpers ----------------
__device__ __forceinline__ uint32_t pkbf(float lo, float hi) {
    uint32_t r;
    asm("cvt.rn.bf16x2.f32 %0, %1, %2;" : "=r"(r) : "f"(hi), "f"(lo));
    return r;
}
__device__ __forceinline__ void split_bf(const float* x, uint32_t* hi, uint32_t* lo) {
    #pragma unroll
    for (int p = 0; p < 16; p++) {
        float x0 = x[2 * p], x1 = x[2 * p + 1];
        uint32_t h = pkbf(x0, x1);
        float r0 = x0 - __uint_as_float(h << 16);
        float r1 = x1 - __uint_as_float(h & 0xffff0000u);
        hi[p] = h;
        lo[p] = pkbf(r0, r1);
    }
}
// pack one B-fragment quad {hi0,hi1,lo0,lo1} from 4 fp32 weights
__device__ __forceinline__ uint4 pack_bquad(float w00, float w01, float w10, float w11) {
    uint4 q;
    q.x = pkbf(w00, w01);
    q.y = pkbf(w10, w11);
    q.z = pkbf(w00 - __uint_as_float(q.x << 16), w01 - __uint_as_float(q.x & 0xffff0000u));
    q.w = pkbf(w10 - __uint_as_float(q.y << 16), w11 - __uint_as_float(q.y & 0xffff0000u));
    return q;
}
__device__ __forceinline__ void mma16816(float* d, const uint32_t* a,
                                         uint32_t b0, uint32_t b1) {
    asm volatile(
        "mma.sync.aligned.m16n8k16.row.col.f32.bf16.bf16.f32 "
        "{%0,%1,%2,%3}, {%4,%5,%6,%7}, {%8,%9}, {%0,%1,%2,%3};"
        : "+f"(d[0]), "+f"(d[1]), "+f"(d[2]), "+f"(d[3])
        : "r"(a[0]), "r"(a[1]), "r"(a[2]), "r"(a[3]), "r"(b0), "r"(b1));
}

// ---------------- kernel A: build q/k/v tables (520 blocks x 32) ----------------
__global__ void build_qkv(const float* __restrict__ tok_emb,
                          const float* __restrict__ pos_emb,
                          const float* __restrict__ Wq,
                          const float* __restrict__ Wk,
                          const float* __restrict__ Wv) {
    int r    = blockIdx.x;            // 0..519
    int lane = threadIdx.x;           // output col h*8+d
    int s = r / VOCAB, tok = r - s * VOCAB;

    float x = tok_emb[tok * NE + lane] + pos_emb[s * NE + lane];
    int h = lane >> 3, d = lane & 7;

    float qa = 0.f, ka = 0.f, va = 0.f;
    #pragma unroll
    for (int c = 0; c < NE; c++) {
        float xc = __shfl_sync(0xffffffffu, x, c);
        int wi = (h * NE + c) * 8 + d;
        qa = fmaf(xc, Wq[wi], qa);
        ka = fmaf(xc, Wk[wi], ka);
        va = fmaf(xc, Wv[wi], va);
    }
    g_qT[lane * NROWTAB + r] = qa;
    g_kT[lane * NROWTAB + r] = ka;
    g_v [r * NE + lane]      = va;
}

// ---------------- kernel B: QK exp table (coalesced) ----------------
__global__ void build_qk(void) {
    int id = blockIdx.x * 256 + threadIdx.x;
    const int TOTAL = TT * VOCAB * TT * VOCAB;
    if (id >= TOTAL) return;
    int toks = id % VOCAB;
    int r2   = id / VOCAB;
    int s    = r2 & 7;
    int r3   = r2 >> 3;
    int tokt = r3 % VOCAB;
    int t    = r3 / VOCAB;

    int rq = t * VOCAB + tokt;
    int rk = s * VOCAB + toks;

    float dot[4];
    #pragma unroll
    for (int h = 0; h < 4; h++) {
        float acc = 0.f;
        #pragma unroll
        for (int d = 0; d < 8; d++)
            acc = fmaf(g_qT[(h * 8 + d) * NROWTAB + rq],
                       g_kT[(h * 8 + d) * NROWTAB + rk], acc);
        dot[h] = expf(acc * 0.17677669529663687f);   // exp baked in
    }
    g_qk[id] = make_float4(dot[0], dot[1], dot[2], dot[3]);
}

// ---------------- main persistent kernel ----------------
__global__ void __launch_bounds__(512, 1)
bigram_main(const int*   __restrict__ idx,
            const float* __restrict__ Wf,
            const float* __restrict__ bf,
            const float* __restrict__ Wl,
            const float* __restrict__ bl,
            float*       __restrict__ out,
            int n_wtiles) {
    extern __shared__ char sm[];
    float* BFs = (float*)(sm + OFF_BF);
    float* BLs = (float*)(sm + OFF_BL);
    uint4* B1P = (uint4*)(sm + OFF_B1P);
    uint4* B2P = (uint4*)(sm + OFF_B2P);
    float* VT  = (float*)(sm + OFF_VT);
    const int tid = threadIdx.x;

    // ---- one-time init ----
    for (int i = tid; i < NROWTAB * NE; i += 512)
        VT[(i >> 5) * VT_STRIDE + (i & 31)] = g_v[i];
    if (tid < 32) BFs[tid] = bf[tid];
    if (tid < 72) BLs[tid] = (tid < 65) ? bl[tid] : 0.f;

    // B1P: packed fragment quads of WfT. entry ((nt*2+k)*8+lq)*4+lr
    if (tid < 256) {
        int ent = tid;
        int lr = ent & 3, lq = (ent >> 2) & 7, kk = (ent >> 5) & 1, nt = ent >> 6;
        int n  = nt * 8 + lq;
        int e0 = 16 * kk + 2 * lr;
        B1P[ent] = pack_bquad(Wf[e0 * NE + n],       Wf[(e0 + 1) * NE + n],
                              Wf[(e0 + 8) * NE + n], Wf[(e0 + 9) * NE + n]);
    }
    // B2P: packed quads of WlT, cols >= 65 zero
    for (int ent = tid; ent < 576; ent += 512) {
        int lr = ent & 3, lq = (ent >> 2) & 7, kk = (ent >> 5) & 1, nt = ent >> 6;
        int n  = nt * 8 + lq;
        int e0 = 16 * kk + 2 * lr;
        float w00 = 0.f, w01 = 0.f, w10 = 0.f, w11 = 0.f;
        if (n < 65) {
            w00 = Wl[e0 * VOCAB + n];       w01 = Wl[(e0 + 1) * VOCAB + n];
            w10 = Wl[(e0 + 8) * VOCAB + n]; w11 = Wl[(e0 + 9) * VOCAB + n];
        }
        B2P[ent] = pack_bquad(w00, w01, w10, w11);
    }
    __syncthreads();

    const int wid = tid >> 5, l = tid & 31;
    const int lq = l >> 2, lr = l & 3;
    const int t = l & 7;
    char*     WR = sm + OFF_WARP + wid * WARP_BYTES;
    uint32_t* XW = (uint32_t*)WR;      // 32 rows * 33 words (A-frag staging)
    float*    ST = (float*)WR;         // 16 rows * 65 floats (stage, aliased)

    const int wstride = gridDim.x * NWARP;
    int wt = blockIdx.x * NWARP + wid;
    if (wt < n_wtiles) {
        int tk = idx[(size_t)wt * 32 + l];
        while (wt < n_wtiles) {
            // ---- tokens via warp shuffle ----
            int toks[8];
            #pragma unroll
            for (int s = 0; s < 8; s++)
                toks[s] = __shfl_sync(0xffffffffu, tk, (l & 24) | s);
            const int mytok = toks[t];

            // ---- prefetch next tile's idx (covers LDG latency with GEMMs) ----
            int wtn = wt + wstride;
            int tk_next = 0;
            if (wtn < n_wtiles) tk_next = idx[(size_t)wtn * 32 + l];

            // ---- attention (exp pre-baked) ----
            float4 w4[8];
            #pragma unroll
            for (int s = 0; s < 8; s++)
                if (s <= t)
                    w4[s] = g_qk[((t * VOCAB + mytok) * 8 + s) * VOCAB + toks[s]];

            float x2[32];
            #pragma unroll
            for (int h = 0; h < 4; h++) {
                float p[8], ssum = 0.f;
                #pragma unroll
                for (int s = 0; s < 8; s++) {
                    if (s <= t) {
                        p[s] = (h == 0) ? w4[s].x : (h == 1) ? w4[s].y
                             : (h == 2) ? w4[s].z : w4[s].w;
                        ssum += p[s];
                    }
                }
                float inv = __fdividef(1.f, ssum);
                float oh[8] = {0.f, 0.f, 0.f, 0.f, 0.f, 0.f, 0.f, 0.f};
                #pragma unroll
                for (int s = 0; s < 8; s++) {
                    if (s <= t) {
                        const float* vr = &VT[(s * VOCAB + toks[s]) * VT_STRIDE + h * 8];
                        float4 v0 = *reinterpret_cast<const float4*>(vr);
                        float4 v1 = *reinterpret_cast<const float4*>(vr + 4);
                        float ws = p[s];
                        oh[0] = fmaf(ws, v0.x, oh[0]); oh[1] = fmaf(ws, v0.y, oh[1]);
                        oh[2] = fmaf(ws, v0.z, oh[2]); oh[3] = fmaf(ws, v0.w, oh[3]);
                        oh[4] = fmaf(ws, v1.x, oh[4]); oh[5] = fmaf(ws, v1.y, oh[5]);
                        oh[6] = fmaf(ws, v1.z, oh[6]); oh[7] = fmaf(ws, v1.w, oh[7]);
                    }
                }
                #pragma unroll
                for (int d = 0; d < 8; d++) x2[h * 8 + d] = oh[d] * inv;
            }

            // ---- stage x2 split bf16 ----
            {
                uint32_t hi[16], lo[16];
                split_bf(x2, hi, lo);
                uint32_t* xr = XW + l * 33;
                #pragma unroll
                for (int p = 0; p < 16; p++) { xr[p] = hi[p]; xr[16 + p] = lo[p]; }
            }
            __syncwarp();

            // ---- A fragments for GEMM1 ----
            uint32_t ah[2][2][4], al[2][2][4];
            #pragma unroll
            for (int m = 0; m < 2; m++) {
                int r0 = (m * 16 + lq) * 33, r1 = r0 + 8 * 33;
                #pragma unroll
                for (int k = 0; k < 2; k++) {
                    int w0 = 8 * k + lr;
                    ah[m][k][0] = XW[r0 + w0];     ah[m][k][1] = XW[r1 + w0];
                    ah[m][k][2] = XW[r0 + w0 + 4]; ah[m][k][3] = XW[r1 + w0 + 4];
                    al[m][k][0] = XW[r0 + 16 + w0];     al[m][k][1] = XW[r1 + 16 + w0];
                    al[m][k][2] = XW[r0 + 16 + w0 + 4]; al[m][k][3] = XW[r1 + 16 + w0 + 4];
                }
            }
            __syncwarp();   // XW reads done; region reused as ST below

            // ---- GEMM1: D1 = X @ WfT (3-term split, packed B) ----
            float D1[2][4][4];
            #pragma unroll
            for (int m = 0; m < 2; m++)
                #pragma unroll
                for (int n = 0; n < 4; n++)
                    #pragma unroll
                    for (int q = 0; q < 4; q++) D1[m][n][q] = 0.f;

            #pragma unroll
            for (int nt = 0; nt < 4; nt++) {
                #pragma unroll
                for (int k = 0; k < 2; k++) {
                    uint4 b = B1P[((nt * 2 + k) * 8 + lq) * 4 + lr];
                    #pragma unroll
                    for (int m = 0; m < 2; m++) {
                        mma16816(D1[m][nt], ah[m][k], b.x, b.y);
                        mma16816(D1[m][nt], ah[m][k], b.z, b.w);
                        mma16816(D1[m][nt], al[m][k], b.x, b.y);
                    }
                }
            }

            // ---- relu(+bias) -> GEMM2 A fragments (registers only) ----
            uint32_t fh[2][2][4], fl[2][2][4];
            #pragma unroll
            for (int m = 0; m < 2; m++) {
                #pragma unroll
                for (int nt = 0; nt < 4; nt++) {
                    int col = nt * 8 + lr * 2;
                    float c0 = fmaxf(D1[m][nt][0] + BFs[col],     0.f);
                    float c1 = fmaxf(D1[m][nt][1] + BFs[col + 1], 0.f);
                    float c2 = fmaxf(D1[m][nt][2] + BFs[col],     0.f);
                    float c3 = fmaxf(D1[m][nt][3] + BFs[col + 1], 0.f);
                    uint32_t h01 = pkbf(c0, c1);
                    uint32_t h23 = pkbf(c2, c3);
                    float r0 = c0 - __uint_as_float(h01 << 16);
                    float r1 = c1 - __uint_as_float(h01 & 0xffff0000u);
                    float r2 = c2 - __uint_as_float(h23 << 16);
                    float r3 = c3 - __uint_as_float(h23 & 0xffff0000u);
                    int K = nt >> 1, pc = nt & 1;
                    fh[m][K][2 * pc]     = h01;
                    fh[m][K][2 * pc + 1] = h23;
                    fl[m][K][2 * pc]     = pkbf(r0, r1);
                    fl[m][K][2 * pc + 1] = pkbf(r2, r3);
                }
            }

            // ---- GEMM2 per m-half: 3 short chains -> stride-65 stage -> flush ----
            #pragma unroll
            for (int m = 0; m < 2; m++) {
                #pragma unroll
                for (int nt = 0; nt < 9; nt++) {
                    uint4 b0 = B2P[((nt * 2 + 0) * 8 + lq) * 4 + lr];
                    uint4 b1 = B2P[((nt * 2 + 1) * 8 + lq) * 4 + lr];
                    float Da[4] = {0.f, 0.f, 0.f, 0.f};
                    float Db[4] = {0.f, 0.f, 0.f, 0.f};
                    float Dc[4] = {0.f, 0.f, 0.f, 0.f};
                    mma16816(Da, fh[m][0], b0.x, b0.y);
                    mma16816(Db, fh[m][0], b0.z, b0.w);
                    mma16816(Dc, fl[m][0], b0.x, b0.y);
                    mma16816(Da, fh[m][1], b1.x, b1.y);
                    mma16816(Db, fh[m][1], b1.z, b1.w);
                    mma16816(Dc, fl[m][1], b1.x, b1.y);
                    int col = nt * 8 + lr * 2;
                    int r0 = lq * 65, r1 = r0 + 8 * 65;
                    if (nt < 8) {
                        ST[r0 + col]     = Da[0] + Db[0] + Dc[0] + BLs[col];
                        ST[r0 + col + 1] = Da[1] + Db[1] + Dc[1] + BLs[col + 1];
                        ST[r1 + col]     = Da[2] + Db[2] + Dc[2] + BLs[col];
                        ST[r1 + col + 1] = Da[3] + Db[3] + Dc[3] + BLs[col + 1];
                    } else if (lr == 0) {
                        ST[r0 + 64] = Da[0] + Db[0] + Dc[0] + BLs[64];
                        ST[r1 + 64] = Da[2] + Db[2] + Dc[2] + BLs[64];
                    }
                }
                __syncwarp();

                // contiguous flush: 16 rows * 65 f = 260 float4
                float4*       og = (float4*)(out + ((size_t)wt * 32 + m * 16) * 65);
                const float4* s4 = (const float4*)ST;
                #pragma unroll
                for (int i = 0; i < 8; i++) og[i * 32 + l] = s4[i * 32 + l];
                if (l < 4) og[256 + l] = s4[256 + l];
                __syncwarp();
            }

            wt = wtn;
            tk = tk_next;
        }
    }
}

// ---------------- launch ----------------
extern "C" void kernel_launch(void* const* d_in, const int* in_sizes, int n_in,
                              void* d_out, int out_size) {
    const int*   idx     = (const int*)  d_in[0];
    const float* tok_emb = (const float*)d_in[1];
    const float* pos_emb = (const float*)d_in[2];
    const float* Wq      = (const float*)d_in[3];
    const float* Wk      = (const float*)d_in[4];
    const float* Wv      = (const float*)d_in[5];
    const float* Wf      = (const float*)d_in[6];
    const float* bf      = (const float*)d_in[7];
    const float* Wl      = (const float*)d_in[8];
    const float* bl      = (const float*)d_in[9];
    float* out = (float*)d_out;

    build_qkv<<<NROWTAB, 32>>>(tok_emb, pos_emb, Wq, Wk, Wv);
    build_qk<<<(TT * VOCAB * TT * VOCAB + 255) / 256, 256>>>();

    int dev = 0, smc = 148;
    cudaGetDevice(&dev);
    cudaDeviceGetAttribute(&smc, cudaDevAttrMultiProcessorCount, dev);

    cudaFuncSetAttribute(bigram_main,
                         cudaFuncAttributeMaxDynamicSharedMemorySize, SMEM_TOTAL);
    int n_wtiles = in_sizes[0] / 32;     // 1,048,576 / 32 = 32768
    bigram_main<<<smc, 512, SMEM_TOTAL>>>(idx, Wf, bf, Wl, bl, out, n_wtiles);
}

// round 13
// speedup vs baseline: 2.5586x; 1.0682x over previous
#include <cuda_runtime.h>
#include <cuda_bf16.h>
#include <cstdint>

// BigramLM fused kernel for GB300 (sm_103a) — HMMA, pipelined QK lookups.
//  - QK table stores exp(q.k*scale); attention is adds+fma only.
//  - 512 threads persistent (4 warps/SMSP), warp-decoupled tiles of 32 rows.
//  - QK-table lookups (w4) prefetched ONE TILE AHEAD: the ~250-cyc scattered-L2
//    latency drains behind the GEMM phase instead of stalling the tile top.
//  - x2 staging rows padded to 36 words -> 8 STS.128 (conflict-free).
//  - B fragments pre-packed as uint4 quads; GEMM2 = 3 independent 2-deep chains.
//  - Logits stage stride 65 -> contiguous float4 flush.
//  - build_qkv: W staged coalesced in smem (was 96 uncoalesced LDG/warp).

#define VOCAB 65
#define NE    32
#define TT    8
#define NROWTAB 520
#define VT_STRIDE 36
#define NWARP 16

// ---- smem byte offsets ----
#define OFF_BF     0          // 32 f
#define OFF_BL     128        // 72 f
#define OFF_B1P    416        // 256 uint4 = 4096
#define OFF_B2P    4512       // 576 uint4 = 9216
#define OFF_VT     13728      // 520*36 f = 74880
#define OFF_WARP   88608      // 16 warps * 4608 (XW 32*36 words, aliased 16x65-f stage)
#define WARP_BYTES 4608
#define SMEM_TOTAL (88608 + NWARP * WARP_BYTES)   // 162336

// ---------------- scratch ----------------
__device__ float  g_qT[NE * NROWTAB];   // transposed for coalesced build_qk
__device__ float  g_kT[NE * NROWTAB];
__device__ float  g_v [NROWTAB * NE];
__device__ float4 g_qk[TT * VOCAB * TT * VOCAB];   // exp(dot*scale), 4 heads

// ---------------- helpers ----------------
__device__ __forceinline__ uint32_t pkbf(float lo, float hi) {
    uint32_t r;
    asm("cvt.rn.bf16x2.f32 %0, %1, %2;" : "=r"(r) : "f"(hi), "f"(lo));
    return r;
}
__device__ __forceinline__ void split_bf(const float* x, uint32_t* hi, uint32_t* lo) {
    #pragma unroll
    for (int p = 0; p < 16; p++) {
        float x0 = x[2 * p], x1 = x[2 * p + 1];
        uint32_t h = pkbf(x0, x1);
        float r0 = x0 - __uint_as_float(h << 16);
        float r1 = x1 - __uint_as_float(h & 0xffff0000u);
        hi[p] = h;
        lo[p] = pkbf(r0, r1);
    }
}
// pack one B-fragment quad {hi0,hi1,lo0,lo1} from 4 fp32 weights
__device__ __forceinline__ uint4 pack_bquad(float w00, float w01, float w10, float w11) {
    uint4 q;
    q.x = pkbf(w00, w01);
    q.y = pkbf(w10, w11);
    q.z = pkbf(w00 - __uint_as_float(q.x << 16), w01 - __uint_as_float(q.x & 0xffff0000u));
    q.w = pkbf(w10 - __uint_as_float(q.y << 16), w11 - __uint_as_float(q.y & 0xffff0000u));
    return q;
}
__device__ __forceinline__ void mma16816(float* d, const uint32_t* a,
                                         uint32_t b0, uint32_t b1) {
    asm volatile(
        "mma.sync.aligned.m16n8k16.row.col.f32.bf16.bf16.f32 "
        "{%0,%1,%2,%3}, {%4,%5,%6,%7}, {%8,%9}, {%0,%1,%2,%3};"
        : "+f"(d[0]), "+f"(d[1]), "+f"(d[2]), "+f"(d[3])
        : "r"(a[0]), "r"(a[1]), "r"(a[2]), "r"(a[3]), "r"(b0), "r"(b1));
}

// ---------------- kernel A: build q/k/v tables (65 blocks x 256) ----------------
__global__ void build_qkv(const float* __restrict__ tok_emb,
                          const float* __restrict__ pos_emb,
                          const float* __restrict__ Wq,
                          const float* __restrict__ Wk,
                          const float* __restrict__ Wv) {
    __shared__ float sWq[1024], sWk[1024], sWv[1024];
    int tid = threadIdx.x;
    for (int i = tid; i < 1024; i += 256) {
        sWq[i] = Wq[i]; sWk[i] = Wk[i]; sWv[i] = Wv[i];
    }
    __syncthreads();

    int r    = blockIdx.x * 8 + (tid >> 5);   // 0..519
    int lane = tid & 31;
    if (r >= NROWTAB) return;
    int s = r / VOCAB, tok = r - s * VOCAB;

    float x = tok_emb[tok * NE + lane] + pos_emb[s * NE + lane];
    int h = lane >> 3, d = lane & 7;

    float qa = 0.f, ka = 0.f, va = 0.f;
    #pragma unroll
    for (int c = 0; c < NE; c++) {
        float xc = __shfl_sync(0xffffffffu, x, c);
        int wi = (h * NE + c) * 8 + d;
        qa = fmaf(xc, sWq[wi], qa);
        ka = fmaf(xc, sWk[wi], ka);
        va = fmaf(xc, sWv[wi], va);
    }
    g_qT[lane * NROWTAB + r] = qa;
    g_kT[lane * NROWTAB + r] = ka;
    g_v [r * NE + lane]      = va;
}

// ---------------- kernel B: QK exp table (coalesced) ----------------
__global__ void build_qk(void) {
    int id = blockIdx.x * 256 + threadIdx.x;
    const int TOTAL = TT * VOCAB * TT * VOCAB;
    if (id >= TOTAL) return;
    int toks = id % VOCAB;
    int r2   = id / VOCAB;
    int s    = r2 & 7;
    int r3   = r2 >> 3;
    int tokt = r3 % VOCAB;
    int t    = r3 / VOCAB;

    int rq = t * VOCAB + tokt;
    int rk = s * VOCAB + toks;

    float dot[4];
    #pragma unroll
    for (int h = 0; h < 4; h++) {
        float acc = 0.f;
        #pragma unroll
        for (int d = 0; d < 8; d++)
            acc = fmaf(g_qT[(h * 8 + d) * NROWTAB + rq],
                       g_kT[(h * 8 + d) * NROWTAB + rk], acc);
        dot[h] = expf(acc * 0.17677669529663687f);   // exp baked in
    }
    g_qk[id] = make_float4(dot[0], dot[1], dot[2], dot[3]);
}

// ---------------- main persistent kernel ----------------
__global__ void __launch_bounds__(512, 1)
bigram_main(const int*   __restrict__ idx,
            const float* __restrict__ Wf,
            const float* __restrict__ bf,
            const float* __restrict__ Wl,
            const float* __restrict__ bl,
            float*       __restrict__ out,
            int n_wtiles) {
    extern __shared__ char sm[];
    float* BFs = (float*)(sm + OFF_BF);
    float* BLs = (float*)(sm + OFF_BL);
    uint4* B1P = (uint4*)(sm + OFF_B1P);
    uint4* B2P = (uint4*)(sm + OFF_B2P);
    float* VT  = (float*)(sm + OFF_VT);
    const int tid = threadIdx.x;

    // ---- one-time init ----
    for (int i = tid; i < NROWTAB * NE; i += 512)
        VT[(i >> 5) * VT_STRIDE + (i & 31)] = g_v[i];
    if (tid < 32) BFs[tid] = bf[tid];
    if (tid < 72) BLs[tid] = (tid < 65) ? bl[tid] : 0.f;

    // B1P: packed fragment quads of WfT. entry ((nt*2+k)*8+lq)*4+lr
    if (tid < 256) {
        int ent = tid;
        int lr = ent & 3, lq = (ent >> 2) & 7, kk = (ent >> 5) & 1, nt = ent >> 6;
        int n  = nt * 8 + lq;
        int e0 = 16 * kk + 2 * lr;
        B1P[ent] = pack_bquad(Wf[e0 * NE + n],       Wf[(e0 + 1) * NE + n],
                              Wf[(e0 + 8) * NE + n], Wf[(e0 + 9) * NE + n]);
    }
    // B2P: packed quads of WlT, cols >= 65 zero
    for (int ent = tid; ent < 576; ent += 512) {
        int lr = ent & 3, lq = (ent >> 2) & 7, kk = (ent >> 5) & 1, nt = ent >> 6;
        int n  = nt * 8 + lq;
        int e0 = 16 * kk + 2 * lr;
        float w00 = 0.f, w01 = 0.f, w10 = 0.f, w11 = 0.f;
        if (n < 65) {
            w00 = Wl[e0 * VOCAB + n];       w01 = Wl[(e0 + 1) * VOCAB + n];
            w10 = Wl[(e0 + 8) * VOCAB + n]; w11 = Wl[(e0 + 9) * VOCAB + n];
        }
        B2P[ent] = pack_bquad(w00, w01, w10, w11);
    }
    __syncthreads();

    const int wid = tid >> 5, l = tid & 31;
    const int lq = l >> 2, lr = l & 3;
    const int t = l & 7;
    char*     WR = sm + OFF_WARP + wid * WARP_BYTES;
    uint32_t* XW = (uint32_t*)WR;      // 32 rows * 36 words (A-frag staging, 16B-aligned rows)
    float*    ST = (float*)WR;         // 16 rows * 65 floats (stage, aliased)

    const int wstride = gridDim.x * NWARP;
    int wt = blockIdx.x * NWARP + wid;
    if (wt < n_wtiles) {
        // ---- peel: first tile's tokens + QK lookups ----
        int tk = idx[(size_t)wt * 32 + l];
        float4 w4[8];
        {
            int tks[8];
            #pragma unroll
            for (int s = 0; s < 8; s++) tks[s] = __shfl_sync(0xffffffffu, tk, (l & 24) | s);
            #pragma unroll
            for (int s = 0; s < 8; s++)
                if (s <= t)
                    w4[s] = g_qk[((t * VOCAB + tks[t]) * 8 + s) * VOCAB + tks[s]];
        }

        while (wt < n_wtiles) {
            const int wtn = wt + wstride;

            // ---- tokens (recomputed from tk; cheap shuffles) ----
            int toks[8];
            #pragma unroll
            for (int s = 0; s < 8; s++)
                toks[s] = __shfl_sync(0xffffffffu, tk, (l & 24) | s);

            // ---- prefetch next tile's idx ----
            int tk_next = 0;
            if (wtn < n_wtiles) tk_next = idx[(size_t)wtn * 32 + l];

            // ---- attention: softmax from prefetched w4 + smem V-sum ----
            float x2[32];
            #pragma unroll
            for (int h = 0; h < 4; h++) {
                float p[8], ssum = 0.f;
                #pragma unroll
                for (int s = 0; s < 8; s++) {
                    if (s <= t) {
                        p[s] = (h == 0) ? w4[s].x : (h == 1) ? w4[s].y
                             : (h == 2) ? w4[s].z : w4[s].w;
                        ssum += p[s];
                    }
                }
                float inv = __fdividef(1.f, ssum);
                float oh[8] = {0.f, 0.f, 0.f, 0.f, 0.f, 0.f, 0.f, 0.f};
                #pragma unroll
                for (int s = 0; s < 8; s++) {
                    if (s <= t) {
                        const float* vr = &VT[(s * VOCAB + toks[s]) * VT_STRIDE + h * 8];
                        float4 v0 = *reinterpret_cast<const float4*>(vr);
                        float4 v1 = *reinterpret_cast<const float4*>(vr + 4);
                        float ws = p[s];
                        oh[0] = fmaf(ws, v0.x, oh[0]); oh[1] = fmaf(ws, v0.y, oh[1]);
                        oh[2] = fmaf(ws, v0.z, oh[2]); oh[3] = fmaf(ws, v0.w, oh[3]);
                        oh[4] = fmaf(ws, v1.x, oh[4]); oh[5] = fmaf(ws, v1.y, oh[5]);
                        oh[6] = fmaf(ws, v1.z, oh[6]); oh[7] = fmaf(ws, v1.w, oh[7]);
                    }
                }
                #pragma unroll
                for (int d = 0; d < 8; d++) x2[h * 8 + d] = oh[d] * inv;
            }

            // ---- stage x2 split bf16: 8 STS.128 (rows 144B-aligned) ----
            {
                uint32_t hi[16], lo[16];
                split_bf(x2, hi, lo);
                uint4* xr4 = (uint4*)(XW + l * 36);
                #pragma unroll
                for (int q = 0; q < 4; q++)
                    xr4[q] = make_uint4(hi[4 * q], hi[4 * q + 1], hi[4 * q + 2], hi[4 * q + 3]);
                #pragma unroll
                for (int q = 0; q < 4; q++)
                    xr4[4 + q] = make_uint4(lo[4 * q], lo[4 * q + 1], lo[4 * q + 2], lo[4 * q + 3]);
            }
            __syncwarp();

            // ---- A fragments for GEMM1 ----
            uint32_t ah[2][2][4], al[2][2][4];
            #pragma unroll
            for (int m = 0; m < 2; m++) {
                int r0 = (m * 16 + lq) * 36, r1 = r0 + 8 * 36;
                #pragma unroll
                for (int k = 0; k < 2; k++) {
                    int w0 = 8 * k + lr;
                    ah[m][k][0] = XW[r0 + w0];     ah[m][k][1] = XW[r1 + w0];
                    ah[m][k][2] = XW[r0 + w0 + 4]; ah[m][k][3] = XW[r1 + w0 + 4];
                    al[m][k][0] = XW[r0 + 16 + w0];     al[m][k][1] = XW[r1 + 16 + w0];
                    al[m][k][2] = XW[r0 + 16 + w0 + 4]; al[m][k][3] = XW[r1 + 16 + w0 + 4];
                }
            }
            __syncwarp();   // XW reads done; region reused as ST below

            // ---- issue next tile's QK lookups: drain behind the GEMM phase ----
            float4 w4n[8];
            if (wtn < n_wtiles) {
                int tksn[8];
                #pragma unroll
                for (int s = 0; s < 8; s++)
                    tksn[s] = __shfl_sync(0xffffffffu, tk_next, (l & 24) | s);
                #pragma unroll
                for (int s = 0; s < 8; s++)
                    if (s <= t)
                        w4n[s] = g_qk[((t * VOCAB + tksn[t]) * 8 + s) * VOCAB + tksn[s]];
            }

            // ---- GEMM1: D1 = X @ WfT (3-term split, packed B) ----
            float D1[2][4][4];
            #pragma unroll
            for (int m = 0; m < 2; m++)
                #pragma unroll
                for (int n = 0; n < 4; n++)
                    #pragma unroll
                    for (int q = 0; q < 4; q++) D1[m][n][q] = 0.f;

            #pragma unroll
            for (int nt = 0; nt < 4; nt++) {
                #pragma unroll
                for (int k = 0; k < 2; k++) {
                    uint4 b = B1P[((nt * 2 + k) * 8 + lq) * 4 + lr];
                    #pragma unroll
                    for (int m = 0; m < 2; m++) {
                        mma16816(D1[m][nt], ah[m][k], b.x, b.y);
                        mma16816(D1[m][nt], ah[m][k], b.z, b.w);
                        mma16816(D1[m][nt], al[m][k], b.x, b.y);
                    }
                }
            }

            // ---- relu(+bias) -> GEMM2 A fragments (registers only) ----
            uint32_t fh[2][2][4], fl[2][2][4];
            #pragma unroll
            for (int m = 0; m < 2; m++) {
                #pragma unroll
                for (int nt = 0; nt < 4; nt++) {
                    int col = nt * 8 + lr * 2;
                    float c0 = fmaxf(D1[m][nt][0] + BFs[col],     0.f);
                    float c1 = fmaxf(D1[m][nt][1] + BFs[col + 1], 0.f);
                    float c2 = fmaxf(D1[m][nt][2] + BFs[col],     0.f);
                    float c3 = fmaxf(D1[m][nt][3] + BFs[col + 1], 0.f);
                    uint32_t h01 = pkbf(c0, c1);
                    uint32_t h23 = pkbf(c2, c3);
                    float r0 = c0 - __uint_as_float(h01 << 16);
                    float r1 = c1 - __uint_as_float(h01 & 0xffff0000u);
                    float r2 = c2 - __uint_as_float(h23 << 16);
                    float r3 = c3 - __uint_as_float(h23 & 0xffff0000u);
                    int K = nt >> 1, pc = nt & 1;
                    fh[m][K][2 * pc]     = h01;
                    fh[m][K][2 * pc + 1] = h23;
                    fl[m][K][2 * pc]     = pkbf(r0, r1);
                    fl[m][K][2 * pc + 1] = pkbf(r2, r3);
                }
            }

            // ---- GEMM2 per m-half: 3 short chains -> stride-65 stage -> flush ----
            #pragma unroll
            for (int m = 0; m < 2; m++) {
                #pragma unroll
                for (int nt = 0; nt < 9; nt++) {
                    uint4 b0 = B2P[((nt * 2 + 0) * 8 + lq) * 4 + lr];
                    uint4 b1 = B2P[((nt * 2 + 1) * 8 + lq) * 4 + lr];
                    float Da[4] = {0.f, 0.f, 0.f, 0.f};
                    float Db[4] = {0.f, 0.f, 0.f, 0.f};
                    float Dc[4] = {0.f, 0.f, 0.f, 0.f};
                    mma16816(Da, fh[m][0], b0.x, b0.y);
                    mma16816(Db, fh[m][0], b0.z, b0.w);
                    mma16816(Dc, fl[m][0], b0.x, b0.y);
                    mma16816(Da, fh[m][1], b1.x, b1.y);
                    mma16816(Db, fh[m][1], b1.z, b1.w);
                    mma16816(Dc, fl[m][1], b1.x, b1.y);
                    int col = nt * 8 + lr * 2;
                    int r0 = lq * 65, r1 = r0 + 8 * 65;
                    if (nt < 8) {
                        ST[r0 + col]     = Da[0] + Db[0] + Dc[0] + BLs[col];
                        ST[r0 + col + 1] = Da[1] + Db[1] + Dc[1] + BLs[col + 1];
                        ST[r1 + col]     = Da[2] + Db[2] + Dc[2] + BLs[col];
                        ST[r1 + col + 1] = Da[3] + Db[3] + Dc[3] + BLs[col + 1];
                    } else if (lr == 0) {
                        ST[r0 + 64] = Da[0] + Db[0] + Dc[0] + BLs[64];
                        ST[r1 + 64] = Da[2] + Db[2] + Dc[2] + BLs[64];
                    }
                }
                __syncwarp();

                // contiguous flush: 16 rows * 65 f = 260 float4
                float4*       og = (float4*)(out + ((size_t)wt * 32 + m * 16) * 65);
                const float4* s4 = (const float4*)ST;
                #pragma unroll
                for (int i = 0; i < 8; i++) og[i * 32 + l] = s4[i * 32 + l];
                if (l < 4) og[256 + l] = s4[256 + l];
                __syncwarp();
            }

            // ---- rotate pipeline state ----
            wt = wtn;
            tk = tk_next;
            #pragma unroll
            for (int s = 0; s < 8; s++) w4[s] = w4n[s];
        }
    }
}

// ---------------- launch ----------------
extern "C" void kernel_launch(void* const* d_in, const int* in_sizes, int n_in,
                              void* d_out, int out_size) {
    const int*   idx     = (const int*)  d_in[0];
    const float* tok_emb = (const float*)d_in[1];
    const float* pos_emb = (const float*)d_in[2];
    const float* Wq      = (const float*)d_in[3];
    const float* Wk      = (const float*)d_in[4];
    const float* Wv      = (const float*)d_in[5];
    const float* Wf      = (const float*)d_in[6];
    const float* bf      = (const float*)d_in[7];
    const float* Wl      = (const float*)d_in[8];
    const float* bl      = (const float*)d_in[9];
    float* out = (float*)d_out;

    build_qkv<<<65, 256>>>(tok_emb, pos_emb, Wq, Wk, Wv);
    build_qk<<<(TT * VOCAB * TT * VOCAB + 255) / 256, 256>>>();

    int dev = 0, smc = 148;
    cudaGetDevice(&dev);
    cudaDeviceGetAttribute(&smc, cudaDevAttrMultiProcessorCount, dev);

    cudaFuncSetAttribute(bigram_main,
                         cudaFuncAttributeMaxDynamicSharedMemorySize, SMEM_TOTAL);
    int n_wtiles = in_sizes[0] / 32;     // 1,048,576 / 32 = 32768
    bigram_main<<<smc, 512, SMEM_TOTAL>>>(idx, Wf, bf, Wl, bl, out, n_wtiles);
}

// round 15
// speedup vs baseline: 2.9028x; 1.1345x over previous
#include <cuda_runtime.h>
#include <cuda_bf16.h>
#include <cstdint>

// BigramLM fused kernel for GB300 (sm_103a) — single-term fp16 HMMA edition.
//  - QK table stores exp(q.k*scale); attention fp32, adds+fma only.
//  - 512 threads persistent (4 warps/SMSP), warp-decoupled 32-row tiles.
//  - GEMMs SINGLE-TERM fp16 (11-bit mantissa): 52 HMMA/tile vs 156 for the
//    3-term bf16 split. Expected rel_err ~3e-4 (< 1e-3 gate).
//  - B fragments packed as one uint4 per (nt,lane) covering BOTH k-blocks.
//  - QK-table lookups prefetched one tile ahead (drain behind GEMM phase).
//  - x2 staging: rows 20 words (80B), 4 STS.128, conflict-free A-frag reads.
//  - Logits stage stride 65, SCALAR stores (odd-lq float2 was misaligned),
//    contiguous float4 flush.

#define VOCAB 65
#define NE    32
#define TT    8
#define NROWTAB 520
#define VT_STRIDE 36
#define NWARP 16

// ---- smem byte offsets ----
#define OFF_BF     0          // 32 f
#define OFF_BL     128        // 72 f
#define OFF_B1P    416        // 128 uint4 = 2048
#define OFF_B2P    2464       // 288 uint4 = 4608
#define OFF_VT     7072       // 520*36 f = 74880
#define OFF_WARP   81952      // 16 warps * 4224 (XW 32*20 words / ST 16*65 f, aliased)
#define WARP_BYTES 4224
#define SMEM_TOTAL (81952 + NWARP * WARP_BYTES)   // 149536

// ---------------- scratch ----------------
__device__ float  g_qT[NE * NROWTAB];   // transposed for coalesced build_qk
__device__ float  g_kT[NE * NROWTAB];
__device__ float  g_v [NROWTAB * NE];
__device__ float4 g_qk[TT * VOCAB * TT * VOCAB];   // exp(dot*scale), 4 heads

// ---------------- helpers ----------------
// pack two fp32 -> fp16x2 (first arg = low half)
__device__ __forceinline__ uint32_t pkhf(float lo, float hi) {
    uint32_t r;
    asm("{ .reg .f16 l, h;\n\t"
        "cvt.rn.f16.f32 l, %1;\n\t"
        "cvt.rn.f16.f32 h, %2;\n\t"
        "mov.b32 %0, {l, h}; }"
        : "=r"(r) : "f"(lo), "f"(hi));
    return r;
}
__device__ __forceinline__ void mma16816(float* d, const uint32_t* a,
                                         uint32_t b0, uint32_t b1) {
    asm volatile(
        "mma.sync.aligned.m16n8k16.row.col.f32.f16.f16.f32 "
        "{%0,%1,%2,%3}, {%4,%5,%6,%7}, {%8,%9}, {%0,%1,%2,%3};"
        : "+f"(d[0]), "+f"(d[1]), "+f"(d[2]), "+f"(d[3])
        : "r"(a[0]), "r"(a[1]), "r"(a[2]), "r"(a[3]), "r"(b0), "r"(b1));
}

// ---------------- kernel A: build q/k/v tables (65 blocks x 256) ----------------
__global__ void build_qkv(const float* __restrict__ tok_emb,
                          const float* __restrict__ pos_emb,
                          const float* __restrict__ Wq,
                          const float* __restrict__ Wk,
                          const float* __restrict__ Wv) {
    __shared__ float sWq[1024], sWk[1024], sWv[1024];
    int tid = threadIdx.x;
    for (int i = tid; i < 1024; i += 256) {
        sWq[i] = Wq[i]; sWk[i] = Wk[i]; sWv[i] = Wv[i];
    }
    __syncthreads();

    int r    = blockIdx.x * 8 + (tid >> 5);   // 0..519
    int lane = tid & 31;
    if (r >= NROWTAB) return;
    int s = r / VOCAB, tok = r - s * VOCAB;

    float x = tok_emb[tok * NE + lane] + pos_emb[s * NE + lane];
    int h = lane >> 3, d = lane & 7;

    float qa = 0.f, ka = 0.f, va = 0.f;
    #pragma unroll
    for (int c = 0; c < NE; c++) {
        float xc = __shfl_sync(0xffffffffu, x, c);
        int wi = (h * NE + c) * 8 + d;
        qa = fmaf(xc, sWq[wi], qa);
        ka = fmaf(xc, sWk[wi], ka);
        va = fmaf(xc, sWv[wi], va);
    }
    g_qT[lane * NROWTAB + r] = qa;
    g_kT[lane * NROWTAB + r] = ka;
    g_v [r * NE + lane]      = va;
}

// ---------------- kernel B: QK exp table (coalesced) ----------------
__global__ void build_qk(void) {
    int id = blockIdx.x * 256 + threadIdx.x;
    const int TOTAL = TT * VOCAB * TT * VOCAB;
    if (id >= TOTAL) return;
    int toks = id % VOCAB;
    int r2   = id / VOCAB;
    int s    = r2 & 7;
    int r3   = r2 >> 3;
    int tokt = r3 % VOCAB;
    int t    = r3 / VOCAB;

    int rq = t * VOCAB + tokt;
    int rk = s * VOCAB + toks;

    float dot[4];
    #pragma unroll
    for (int h = 0; h < 4; h++) {
        float acc = 0.f;
        #pragma unroll
        for (int d = 0; d < 8; d++)
            acc = fmaf(g_qT[(h * 8 + d) * NROWTAB + rq],
                       g_kT[(h * 8 + d) * NROWTAB + rk], acc);
        dot[h] = expf(acc * 0.17677669529663687f);   // exp baked in
    }
    g_qk[id] = make_float4(dot[0], dot[1], dot[2], dot[3]);
}

// ---------------- main persistent kernel ----------------
__global__ void __launch_bounds__(512, 1)
bigram_main(const int*   __restrict__ idx,
            const float* __restrict__ Wf,
            const float* __restrict__ bf,
            const float* __restrict__ Wl,
            const float* __restrict__ bl,
            float*       __restrict__ out,
            int n_wtiles) {
    extern __shared__ char sm[];
    float* BFs = (float*)(sm + OFF_BF);
    float* BLs = (float*)(sm + OFF_BL);
    uint4* B1P = (uint4*)(sm + OFF_B1P);
    uint4* B2P = (uint4*)(sm + OFF_B2P);
    float* VT  = (float*)(sm + OFF_VT);
    const int tid = threadIdx.x;

    // ---- one-time init ----
    for (int i = tid; i < NROWTAB * NE; i += 512)
        VT[(i >> 5) * VT_STRIDE + (i & 31)] = g_v[i];
    if (tid < 32) BFs[tid] = bf[tid];
    if (tid < 72) BLs[tid] = (tid < 65) ? bl[tid] : 0.f;

    // B1P: fp16 B fragments of WfT, both k-blocks per entry.
    // entry (nt*8+lq)*4+lr = {k0_b0, k0_b1, k1_b0, k1_b1}
    if (tid < 128) {
        int ent = tid;
        int lr = ent & 3, lq = (ent >> 2) & 7, nt = ent >> 5;
        int n  = nt * 8 + lq;
        int e0 = 2 * lr, e1 = 16 + 2 * lr;
        uint4 q;
        q.x = pkhf(Wf[e0 * NE + n],       Wf[(e0 + 1) * NE + n]);
        q.y = pkhf(Wf[(e0 + 8) * NE + n], Wf[(e0 + 9) * NE + n]);
        q.z = pkhf(Wf[e1 * NE + n],       Wf[(e1 + 1) * NE + n]);
        q.w = pkhf(Wf[(e1 + 8) * NE + n], Wf[(e1 + 9) * NE + n]);
        B1P[ent] = q;
    }
    // B2P: same for WlT (N padded to 72, cols >= 65 zero)
    if (tid < 288) {
        int ent = tid;
        int lr = ent & 3, lq = (ent >> 2) & 7, nt = ent >> 5;
        int n  = nt * 8 + lq;
        int e0 = 2 * lr, e1 = 16 + 2 * lr;
        uint4 q = make_uint4(0u, 0u, 0u, 0u);
        if (n < 65) {
            q.x = pkhf(Wl[e0 * VOCAB + n],       Wl[(e0 + 1) * VOCAB + n]);
            q.y = pkhf(Wl[(e0 + 8) * VOCAB + n], Wl[(e0 + 9) * VOCAB + n]);
            q.z = pkhf(Wl[e1 * VOCAB + n],       Wl[(e1 + 1) * VOCAB + n]);
            q.w = pkhf(Wl[(e1 + 8) * VOCAB + n], Wl[(e1 + 9) * VOCAB + n]);
        }
        B2P[ent] = q;
    }
    __syncthreads();

    const int wid = tid >> 5, l = tid & 31;
    const int lq = l >> 2, lr = l & 3;
    const int t = l & 7;
    char*     WR = sm + OFF_WARP + wid * WARP_BYTES;
    uint32_t* XW = (uint32_t*)WR;      // 32 rows * 20 words (A-frag staging)
    float*    ST = (float*)WR;         // 16 rows * 65 floats (stage, aliased)

    const int wstride = gridDim.x * NWARP;
    int wt = blockIdx.x * NWARP + wid;
    if (wt < n_wtiles) {
        // ---- peel: first tile's tokens + QK lookups ----
        int tk = idx[(size_t)wt * 32 + l];
        float4 w4[8];
        {
            int tks[8];
            #pragma unroll
            for (int s = 0; s < 8; s++) tks[s] = __shfl_sync(0xffffffffu, tk, (l & 24) | s);
            #pragma unroll
            for (int s = 0; s < 8; s++)
                if (s <= t)
                    w4[s] = g_qk[((t * VOCAB + tks[t]) * 8 + s) * VOCAB + tks[s]];
        }

        while (wt < n_wtiles) {
            const int wtn = wt + wstride;

            // ---- tokens (recomputed from tk; cheap shuffles) ----
            int toks[8];
            #pragma unroll
            for (int s = 0; s < 8; s++)
                toks[s] = __shfl_sync(0xffffffffu, tk, (l & 24) | s);

            // ---- prefetch next tile's idx ----
            int tk_next = 0;
            if (wtn < n_wtiles) tk_next = idx[(size_t)wtn * 32 + l];

            // ---- attention: softmax from prefetched w4 + smem V-sum ----
            float x2[32];
            #pragma unroll
            for (int h = 0; h < 4; h++) {
                float p[8], ssum = 0.f;
                #pragma unroll
                for (int s = 0; s < 8; s++) {
                    if (s <= t) {
                        p[s] = (h == 0) ? w4[s].x : (h == 1) ? w4[s].y
                             : (h == 2) ? w4[s].z : w4[s].w;
                        ssum += p[s];
                    }
                }
                float inv = __fdividef(1.f, ssum);
                float oh[8] = {0.f, 0.f, 0.f, 0.f, 0.f, 0.f, 0.f, 0.f};
                #pragma unroll
                for (int s = 0; s < 8; s++) {
                    if (s <= t) {
                        const float* vr = &VT[(s * VOCAB + toks[s]) * VT_STRIDE + h * 8];
                        float4 v0 = *reinterpret_cast<const float4*>(vr);
                        float4 v1 = *reinterpret_cast<const float4*>(vr + 4);
                        float ws = p[s];
                        oh[0] = fmaf(ws, v0.x, oh[0]); oh[1] = fmaf(ws, v0.y, oh[1]);
                        oh[2] = fmaf(ws, v0.z, oh[2]); oh[3] = fmaf(ws, v0.w, oh[3]);
                        oh[4] = fmaf(ws, v1.x, oh[4]); oh[5] = fmaf(ws, v1.y, oh[5]);
                        oh[6] = fmaf(ws, v1.z, oh[6]); oh[7] = fmaf(ws, v1.w, oh[7]);
                    }
                }
                #pragma unroll
                for (int d = 0; d < 8; d++) x2[h * 8 + d] = oh[d] * inv;
            }

            // ---- stage x2 as fp16x2: 4 STS.128 (rows 80B) ----
            {
                uint32_t xh[16];
                #pragma unroll
                for (int p = 0; p < 16; p++) xh[p] = pkhf(x2[2 * p], x2[2 * p + 1]);
                uint4* xr4 = (uint4*)(XW + l * 20);
                #pragma unroll
                for (int q = 0; q < 4; q++)
                    xr4[q] = make_uint4(xh[4 * q], xh[4 * q + 1], xh[4 * q + 2], xh[4 * q + 3]);
            }
            __syncwarp();

            // ---- A fragments for GEMM1 (20*lq+lr spans distinct banks) ----
            uint32_t ah[2][2][4];
            #pragma unroll
            for (int m = 0; m < 2; m++) {
                int r0 = (m * 16 + lq) * 20, r1 = r0 + 8 * 20;
                #pragma unroll
                for (int k = 0; k < 2; k++) {
                    int w0 = 8 * k + lr;
                    ah[m][k][0] = XW[r0 + w0];     ah[m][k][1] = XW[r1 + w0];
                    ah[m][k][2] = XW[r0 + w0 + 4]; ah[m][k][3] = XW[r1 + w0 + 4];
                }
            }
            __syncwarp();   // XW reads done; region reused as ST below

            // ---- issue next tile's QK lookups: drain behind the GEMM phase ----
            float4 w4n[8];
            if (wtn < n_wtiles) {
                int tksn[8];
                #pragma unroll
                for (int s = 0; s < 8; s++)
                    tksn[s] = __shfl_sync(0xffffffffu, tk_next, (l & 24) | s);
                #pragma unroll
                for (int s = 0; s < 8; s++)
                    if (s <= t)
                        w4n[s] = g_qk[((t * VOCAB + tksn[t]) * 8 + s) * VOCAB + tksn[s]];
            }

            // ---- GEMM1: D1 = X @ WfT (fp16, 16 MMA) ----
            float D1[2][4][4];
            #pragma unroll
            for (int m = 0; m < 2; m++)
                #pragma unroll
                for (int n = 0; n < 4; n++)
                    #pragma unroll
                    for (int q = 0; q < 4; q++) D1[m][n][q] = 0.f;

            #pragma unroll
            for (int nt = 0; nt < 4; nt++) {
                uint4 b = B1P[(nt * 8 + lq) * 4 + lr];
                #pragma unroll
                for (int m = 0; m < 2; m++) {
                    mma16816(D1[m][nt], ah[m][0], b.x, b.y);
                    mma16816(D1[m][nt], ah[m][1], b.z, b.w);
                }
            }

            // ---- relu(+bias) -> GEMM2 A fragments (registers only) ----
            uint32_t fh[2][2][4];
            #pragma unroll
            for (int m = 0; m < 2; m++) {
                #pragma unroll
                for (int nt = 0; nt < 4; nt++) {
                    int col = nt * 8 + lr * 2;
                    float c0 = fmaxf(D1[m][nt][0] + BFs[col],     0.f);
                    float c1 = fmaxf(D1[m][nt][1] + BFs[col + 1], 0.f);
                    float c2 = fmaxf(D1[m][nt][2] + BFs[col],     0.f);
                    float c3 = fmaxf(D1[m][nt][3] + BFs[col + 1], 0.f);
                    int K = nt >> 1, pc = nt & 1;
                    fh[m][K][2 * pc]     = pkhf(c0, c1);
                    fh[m][K][2 * pc + 1] = pkhf(c2, c3);
                }
            }

            // ---- GEMM2 per m-half: 36 MMA total -> stride-65 stage -> flush ----
            #pragma unroll
            for (int m = 0; m < 2; m++) {
                #pragma unroll
                for (int nt = 0; nt < 9; nt++) {
                    uint4 b = B2P[(nt * 8 + lq) * 4 + lr];
                    float D2[4] = {0.f, 0.f, 0.f, 0.f};
                    mma16816(D2, fh[m][0], b.x, b.y);
                    mma16816(D2, fh[m][1], b.z, b.w);
                    int col = nt * 8 + lr * 2;
                    int r0 = lq * 65, r1 = r0 + 8 * 65;
                    if (nt < 8) {
                        // scalar stores: (lq*65+col)*4 is 8B-aligned only for even lq
                        ST[r0 + col]     = D2[0] + BLs[col];
                        ST[r0 + col + 1] = D2[1] + BLs[col + 1];
                        ST[r1 + col]     = D2[2] + BLs[col];
                        ST[r1 + col + 1] = D2[3] + BLs[col + 1];
                    } else if (lr == 0) {
                        ST[r0 + 64] = D2[0] + BLs[64];
                        ST[r1 + 64] = D2[2] + BLs[64];
                    }
                }
                __syncwarp();

                // contiguous flush: 16 rows * 65 f = 260 float4
                float4*       og = (float4*)(out + ((size_t)wt * 32 + m * 16) * 65);
                const float4* s4 = (const float4*)ST;
                #pragma unroll
                for (int i = 0; i < 8; i++) og[i * 32 + l] = s4[i * 32 + l];
                if (l < 4) og[256 + l] = s4[256 + l];
                __syncwarp();
            }

            // ---- rotate pipeline state ----
            wt = wtn;
            tk = tk_next;
            #pragma unroll
            for (int s = 0; s < 8; s++) w4[s] = w4n[s];
        }
    }
}

// ---------------- launch ----------------
extern "C" void kernel_launch(void* const* d_in, const int* in_sizes, int n_in,
                              void* d_out, int out_size) {
    const int*   idx     = (const int*)  d_in[0];
    const float* tok_emb = (const float*)d_in[1];
    const float* pos_emb = (const float*)d_in[2];
    const float* Wq      = (const float*)d_in[3];
    const float* Wk      = (const float*)d_in[4];
    const float* Wv      = (const float*)d_in[5];
    const float* Wf      = (const float*)d_in[6];
    const float* bf      = (const float*)d_in[7];
    const float* Wl      = (const float*)d_in[8];
    const float* bl      = (const float*)d_in[9];
    float* out = (float*)d_out;

    build_qkv<<<65, 256>>>(tok_emb, pos_emb, Wq, Wk, Wv);
    build_qk<<<(TT * VOCAB * TT * VOCAB + 255) / 256, 256>>>();

    int dev = 0, smc = 148;
    cudaGetDevice(&dev);
    cudaDeviceGetAttribute(&smc, cudaDevAttrMultiProcessorCount, dev);

    cudaFuncSetAttribute(bigram_main,
                         cudaFuncAttributeMaxDynamicSharedMemorySize, SMEM_TOTAL);
    int n_wtiles = in_sizes[0] / 32;     // 1,048,576 / 32 = 32768
    bigram_main<<<smc, 512, SMEM_TOTAL>>>(idx, Wf, bf, Wl, bl, out, n_wtiles);
}